// round 11
// baseline (speedup 1.0000x reference)
#include <cuda_runtime.h>
#include <cuda_bf16.h>
#include <math.h>
#include <stdint.h>

// ===========================================================================
// YOLOv8 head via bf16 mma.sync implicit GEMM (shifted-GEMM conv).
//   conv3x3(pad1) == sum over 9 kernel offsets k of GEMM:
//      D[co, p] += W_k[co, ci] * Xpad[p + off_k, ci]
// R11: R10 conv config (best measured) + ALL auxiliary stages batched:
//      wrepack x6 -> 1 launch, pad_transpose x3 -> 1, decode x3 -> 1.
//      Total 5 launches per call.
// ===========================================================================

#define ATOT 33600

// per-level xpad/ypad region offsets (halves)
#define OFF_P3 262144
#define OFF_P4 27398144
#define OFF_P5 41431040
#define XPAD_TOTAL 48918528

// per-level y2 offsets (floats)
#define Y2_P3 0
#define Y2_P4 26214400
#define Y2_P5 39321600
#define Y2_TOTAL 45875200

// per-level wrep offsets (halves): p5 first
#define WR_P5 0
#define WR_P4 2359296
#define WR_P3 2949120
#define WR_TOTAL 3096576

__device__ __align__(256) __nv_bfloat16 g_xpad[XPAD_TOTAL];
__device__ __align__(256) __nv_bfloat16 g_ypad[XPAD_TOTAL];
__device__ __align__(256) float         g_y2  [Y2_TOTAL];
__device__ __align__(256) __nv_bfloat16 g_wr1 [WR_TOTAL];
__device__ __align__(256) __nv_bfloat16 g_wr2 [WR_TOTAL];

struct LevelParams {
    const __nv_bfloat16* X;
    const __nv_bfloat16* Wr;
    const float* scale;
    const float* bias;
    void* Y;
    int C, W, Wp, Np;
    int start;      // first flat CTA index of this level
    int tiles;      // pixel tiles = ceil(Np/128)
    int cgrp;       // C / 128
};

struct WrepackJobs {            // 6 jobs: {w1,w2} x {p5,p4,p3}
    const float* w[6];
    __nv_bfloat16* wr[6];
    int C[6];
    int start[7];               // element starts (co*C + ci flat), start[6]=total
};

struct PadJobs {                // 3 levels
    const float* in[3];
    __nv_bfloat16* Xp[3];
    int C[3], W[3];
    int start[4];               // block starts
};

struct DecJobs {                // 3 levels
    const float* y2[3];
    const float* wf[3];
    const float* bf[3];
    int C[3], W[3], aoff[3];
    float stride[3];
    int start[4];               // block starts
};

__device__ __forceinline__ uint32_t smem_u32(const void* p) {
    return (uint32_t)__cvta_generic_to_shared(p);
}
__device__ __forceinline__ void cp_async16(uint32_t dst, const void* src) {
    asm volatile("cp.async.cg.shared.global [%0], [%1], 16;"
                 :: "r"(dst), "l"(__cvta_generic_to_global(src)) : "memory");
}
__device__ __forceinline__ void cp_commit() {
    asm volatile("cp.async.commit_group;" ::: "memory");
}
__device__ __forceinline__ void ldsm_x4(uint32_t& r0, uint32_t& r1,
                                        uint32_t& r2, uint32_t& r3, uint32_t a) {
    asm volatile("ldmatrix.sync.aligned.m8n8.x4.shared.b16 {%0,%1,%2,%3}, [%4];"
                 : "=r"(r0), "=r"(r1), "=r"(r2), "=r"(r3) : "r"(a));
}
__device__ __forceinline__ void mma_bf16(float& d0, float& d1, float& d2, float& d3,
                                         uint32_t a0, uint32_t a1, uint32_t a2, uint32_t a3,
                                         uint32_t b0, uint32_t b1) {
    asm volatile(
        "mma.sync.aligned.m16n8k16.row.col.f32.bf16.bf16.f32 "
        "{%0,%1,%2,%3}, {%4,%5,%6,%7}, {%8,%9}, {%0,%1,%2,%3};"
        : "+f"(d0), "+f"(d1), "+f"(d2), "+f"(d3)
        : "r"(a0), "r"(a1), "r"(a2), "r"(a3), "r"(b0), "r"(b1));
}

// ---------------------------------------------------------------------------
// batched weight repack: 6 tensors W(co,ci,3,3) fp32 -> Wrep[k][co][ci] bf16
// ---------------------------------------------------------------------------
__global__ void wrepack_all_kernel(WrepackJobs J)
{
    int idx = blockIdx.x * blockDim.x + threadIdx.x;
    if (idx >= J.start[6]) return;
    int j = 0;
#pragma unroll
    for (int t = 1; t < 6; t++) if (idx >= J.start[t]) j = t;
    int e = idx - J.start[j];                 // co*C + ci
    const int C = J.C[j];
    const float* w = J.w[j];
    __nv_bfloat16* wr = J.wr[j];
#pragma unroll
    for (int k = 0; k < 9; k++)
        wr[(size_t)k * C * C + e] = __float2bfloat16_rn(w[(size_t)e * 9 + k]);
}

// ---------------------------------------------------------------------------
// batched pad+transpose: NCHW fp32 -> Xpad[n][p][ci] bf16 (interior only)
// block = (32,8): one 32px x 32ch tile
// ---------------------------------------------------------------------------
__global__ void pad_all_kernel(PadJobs J)
{
    __shared__ float t[32][33];
    int bx = blockIdx.x;
    int j = 0;
#pragma unroll
    for (int l = 1; l < 3; l++) if (bx >= J.start[l]) j = l;
    int idx = bx - J.start[j];

    const int C = J.C[j], W = J.W[j];
    const int HW = W * W, Wp = W + 2, Np = Wp * Wp;
    const int qtiles = HW >> 5, ctiles = C >> 5;

    const int qt = idx % qtiles;
    const int r  = idx / qtiles;
    const int ct = r % ctiles;
    const int n  = r / ctiles;

    const int q0 = qt * 32, c0 = ct * 32;
    const int tx = threadIdx.x, ty = threadIdx.y;

    const float* inN = J.in[j] + (size_t)n * C * HW;
#pragma unroll
    for (int i = 0; i < 4; i++) {
        int c = c0 + ty + i * 8;
        t[ty + i * 8][tx] = inN[(size_t)c * HW + q0 + tx];
    }
    __syncthreads();
    __nv_bfloat16* XpN = J.Xp[j] + (size_t)n * Np * C;
#pragma unroll
    for (int i = 0; i < 4; i++) {
        int q = q0 + ty + i * 8;
        int py = q / W, px = q - py * W;
        int p = (py + 1) * Wp + px + 1;
        XpN[(size_t)p * C + c0 + tx] = __float2bfloat16_rn(t[tx][ty + i * 8]);
    }
}

// ---------------------------------------------------------------------------
// batched conv GEMM over 3 levels: D[128 co x 128 px] = sum Wrep_k * Xpad(+off)
// 8 warps (2M x 4N), warp tile 64x32, mma m16n8k16 bf16, K-chunk 64,
// 3-stage cp.async pipeline, ldmatrix fragments. Level from flat blockIdx.x.
// mode 0: bf16 padded [p][co]; mode 1: fp32 [q][co].
// ---------------------------------------------------------------------------
#define KS      72                      // halves per smem row (64 + 8 pad)
#define STAGEH  (2 * 128 * KS)          // halves per stage (A tile + B tile)
#define OSTRIDE 132

__global__ void __launch_bounds__(256, 2)
conv_gemm_kernel(LevelParams l0, LevelParams l1, LevelParams l2, int mode)
{
    extern __shared__ __nv_bfloat16 dsm[];   // 3 stages of [A(128xKS) | B(128xKS)]

    const int x = blockIdx.x;
    const LevelParams L = (x >= l2.start) ? l2 : ((x >= l1.start) ? l1 : l0);

    const int idx  = x - L.start;
    const int tile = idx % L.tiles;
    const int rest = idx / L.tiles;
    const int cog  = rest % L.cgrp;
    const int n    = rest / L.cgrp;

    const int C = L.C, W = L.W, Wp = L.Wp, Np = L.Np;
    const int p0  = tile * 128;
    const int co0 = cog * 128;

    const int tid    = threadIdx.x;
    const int lane   = tid & 31;
    const int wid    = tid >> 5;
    const int warp_m = wid >> 2;        // 0..1
    const int warp_n = wid & 3;         // 0..3

    const __nv_bfloat16* Ximg = L.X + (size_t)n * Np * C;
    const __nv_bfloat16* wrep = L.Wr;
    const int NC = 9 * (C >> 6);        // K-chunks of 64 ci

    float acc[4][4][4];
#pragma unroll
    for (int mi = 0; mi < 4; mi++)
#pragma unroll
        for (int ni = 0; ni < 4; ni++)
#pragma unroll
            for (int r = 0; r < 4; r++) acc[mi][ni][r] = 0.f;

    const uint32_t smem0 = smem_u32(dsm);

    auto load_chunk = [&](int c, int buf) {
        const int k   = c % 9;
        const int cic = c / 9;
        const int off = (k / 3 - 1) * Wp + (k % 3 - 1);
        const __nv_bfloat16* Asrc = wrep + ((size_t)k * C + co0) * C + cic * 64;
        const __nv_bfloat16* Bsrc = Ximg + (long long)(p0 + off) * C + cic * 64;
        const uint32_t sAb = smem0 + buf * (STAGEH * 2);
        const uint32_t sBb = sAb + 128 * KS * 2;
#pragma unroll
        for (int i = 0; i < 4; i++) {
            int e = tid + i * 256, r = e >> 3, f = e & 7;
            cp_async16(sAb + (r * KS + f * 8) * 2, Asrc + (size_t)r * C + f * 8);
            cp_async16(sBb + (r * KS + f * 8) * 2, Bsrc + (long long)r * C + f * 8);
        }
        cp_commit();
    };

    // per-thread ldmatrix byte offsets (stage-relative)
    uint32_t aOff[4], bOff[2];
#pragma unroll
    for (int mi = 0; mi < 4; mi++) {
        int row = warp_m * 64 + mi * 16 + (lane & 15);
        aOff[mi] = (uint32_t)((row * KS + ((lane >> 4) << 3)) * 2);
    }
#pragma unroll
    for (int np = 0; np < 2; np++) {
        int px = warp_n * 32 + np * 16 + ((lane >> 4) << 3) + (lane & 7);
        bOff[np] = (uint32_t)((px * KS + (((lane >> 3) & 1) << 3)) * 2) + 128 * KS * 2;
    }

    load_chunk(0, 0);
    if (NC > 1) load_chunk(1, 1);

    int buf = 0;
    for (int c = 0; c < NC; c++) {
        if (c + 1 < NC)
            asm volatile("cp.async.wait_group 1;" ::: "memory");
        else
            asm volatile("cp.async.wait_group 0;" ::: "memory");
        __syncthreads();

        if (c + 2 < NC) {
            int nb = buf + 2; if (nb >= 3) nb -= 3;
            load_chunk(c + 2, nb);
        }

        const uint32_t sbase = smem0 + buf * (STAGEH * 2);
#pragma unroll
        for (int ks = 0; ks < 4; ks++) {
            const uint32_t ko = ks * 32;    // 16 halves
            uint32_t af[4][4], bf[2][4];
#pragma unroll
            for (int mi = 0; mi < 4; mi++)
                ldsm_x4(af[mi][0], af[mi][1], af[mi][2], af[mi][3],
                        sbase + aOff[mi] + ko);
#pragma unroll
            for (int np = 0; np < 2; np++)
                ldsm_x4(bf[np][0], bf[np][1], bf[np][2], bf[np][3],
                        sbase + bOff[np] + ko);
#pragma unroll
            for (int mi = 0; mi < 4; mi++)
#pragma unroll
                for (int ni = 0; ni < 4; ni++)
                    mma_bf16(acc[mi][ni][0], acc[mi][ni][1], acc[mi][ni][2], acc[mi][ni][3],
                             af[mi][0], af[mi][1], af[mi][2], af[mi][3],
                             bf[ni >> 1][(ni & 1) * 2], bf[ni >> 1][(ni & 1) * 2 + 1]);
        }
        buf++; if (buf == 3) buf = 0;
    }
    __syncthreads();

    // ---- epilogue: BN+ReLU, stage [px][co] fp32 tile in smem ----
    float* st = (float*)dsm;
    {
        const int g  = lane >> 2;
        const int q2 = (lane & 3) << 1;
#pragma unroll
        for (int mi = 0; mi < 4; mi++) {
            const int col0 = warp_m * 64 + mi * 16 + g;
            const float s0 = __ldg(L.scale + co0 + col0),     b0 = __ldg(L.bias + co0 + col0);
            const float s1 = __ldg(L.scale + co0 + col0 + 8), b1 = __ldg(L.bias + co0 + col0 + 8);
#pragma unroll
            for (int ni = 0; ni < 4; ni++) {
                const int pxl = warp_n * 32 + ni * 8 + q2;
                st[pxl * OSTRIDE + col0]           = fmaxf(fmaf(acc[mi][ni][0], s0, b0), 0.f);
                st[(pxl + 1) * OSTRIDE + col0]     = fmaxf(fmaf(acc[mi][ni][1], s0, b0), 0.f);
                st[pxl * OSTRIDE + col0 + 8]       = fmaxf(fmaf(acc[mi][ni][2], s1, b1), 0.f);
                st[(pxl + 1) * OSTRIDE + col0 + 8] = fmaxf(fmaf(acc[mi][ni][3], s1, b1), 0.f);
            }
        }
    }
    __syncthreads();

#pragma unroll 1
    for (int i = 0; i < 16; i++) {
        int idx2 = tid + i * 256;
        int r = idx2 >> 5, f = idx2 & 31;
        int p = p0 + r;
        if (p < Np) {
            int py = p / Wp, px = p - py * Wp;
            if (py >= 1 && py <= W && px >= 1 && px <= W) {
                float4 v = *(const float4*)&st[r * OSTRIDE + f * 4];
                if (mode == 0) {
                    __nv_bfloat16* Yb = (__nv_bfloat16*)L.Y + (size_t)n * Np * C;
                    __nv_bfloat162 h0 = __floats2bfloat162_rn(v.x, v.y);
                    __nv_bfloat162 h1 = __floats2bfloat162_rn(v.z, v.w);
                    uint2 pk;
                    pk.x = *reinterpret_cast<uint32_t*>(&h0);
                    pk.y = *reinterpret_cast<uint32_t*>(&h1);
                    *(uint2*)&Yb[(size_t)p * C + co0 + f * 4] = pk;
                } else {
                    float* Yf = (float*)L.Y + (size_t)n * (size_t)(W * W) * C;
                    *(float4*)&Yf[((size_t)(py - 1) * W + (px - 1)) * C + co0 + f * 4] = v;
                }
            }
        }
    }
}

// ---------------------------------------------------------------------------
// batched 1x1 conv (C->5) + decode + sigmoid. warp-per-pixel.
// ---------------------------------------------------------------------------
__global__ void __launch_bounds__(256)
decode_all_kernel(DecJobs J, float* __restrict__ out)
{
    __shared__ float s_wf[5 * 512];

    int bx = blockIdx.x;
    int j = 0;
#pragma unroll
    for (int l = 1; l < 3; l++) if (bx >= J.start[l]) j = l;
    int idx = bx - J.start[j];

    const int C = J.C[j], W = J.W[j];
    const int HW = W * W;
    const int qblocks = HW >> 3;
    const int qb = idx % qblocks;
    const int n  = idx / qblocks;

    const float* wf = J.wf[j];
    for (int t = threadIdx.x; t < 5 * C; t += 256) s_wf[t] = wf[t];
    __syncthreads();

    const int wid  = threadIdx.x >> 5;
    const int lane = threadIdx.x & 31;
    const int q = qb * 8 + wid;

    const float* yq = J.y2[j] + ((size_t)n * HW + q) * C;
    float a[5] = {0.f, 0.f, 0.f, 0.f, 0.f};
    const int iters = C >> 7;
    for (int it = 0; it < iters; it++) {
        int cb = it * 128 + lane * 4;
        float4 v = *(const float4*)(yq + cb);
#pragma unroll
        for (int jj = 0; jj < 5; jj++) {
            const float* wj = s_wf + jj * C + cb;
            a[jj] += v.x * wj[0] + v.y * wj[1] + v.z * wj[2] + v.w * wj[3];
        }
    }
#pragma unroll
    for (int jj = 0; jj < 5; jj++)
#pragma unroll
        for (int o = 16; o; o >>= 1)
            a[jj] += __shfl_xor_sync(0xffffffffu, a[jj], o);

    if (lane == 0) {
        const float* bf = J.bf[j];
        const float stride = J.stride[j];
        float a0 = a[0] + bf[0], a1 = a[1] + bf[1], a2 = a[2] + bf[2];
        float a3 = a[3] + bf[3], a4 = a[4] + bf[4];
        int py = q / W, px = q - py * W;
        float ax = px + 0.5f, ay = py + 0.5f;
        float cx = (ax + 0.5f * (a2 - a0)) * stride;
        float cy = (ay + 0.5f * (a3 - a1)) * stride;
        float bw = (a2 + a0) * stride;
        float bh = (a3 + a1) * stride;
        float cls = 1.f / (1.f + expf(-a4));
        size_t base = (size_t)n * 5 * ATOT + (size_t)J.aoff[j] + q;
        out[base]                    = cx;
        out[base + (size_t)ATOT]     = cy;
        out[base + 2 * (size_t)ATOT] = bw;
        out[base + 3 * (size_t)ATOT] = bh;
        out[base + 4 * (size_t)ATOT] = cls;
    }
}

// ---------------------------------------------------------------------------
// Host
// ---------------------------------------------------------------------------
#define CONV_SMEM (3 * STAGEH * 2)   // 110,592 B

extern "C" void kernel_launch(void* const* d_in, const int* in_sizes, int n_in,
                              void* d_out, int out_size)
{
    __nv_bfloat16 *xpad, *ypad, *wr1, *wr2;
    float *y2;
    cudaGetSymbolAddress((void**)&xpad, g_xpad);
    cudaGetSymbolAddress((void**)&ypad, g_ypad);
    cudaGetSymbolAddress((void**)&y2,   g_y2);
    cudaGetSymbolAddress((void**)&wr1,  g_wr1);
    cudaGetSymbolAddress((void**)&wr2,  g_wr2);

    cudaFuncSetAttribute(conv_gemm_kernel,
                         cudaFuncAttributeMaxDynamicSharedMemorySize, CONV_SMEM);

    const int B = in_sizes[0] / (128 * 160 * 160);
    float* out = (float*)d_out;

    // level static tables: order p5, p4, p3 (longest conv CTAs first)
    const int   Cs[3]   = {512, 256, 128};
    const int   Ws[3]   = {40, 80, 160};
    const int   xin[3]  = {2, 1, 0};
    const int   widx[3] = {19, 11, 3};
    const int   xoff[3] = {OFF_P5, OFF_P4, OFF_P3};
    const int   y2off[3]= {Y2_P5, Y2_P4, Y2_P3};
    const int   wroff[3]= {WR_P5, WR_P4, WR_P3};
    const int   aoff[3] = {32000, 25600, 0};
    const float strd[3] = {32.f, 16.f, 8.f};

    // ---- batched wrepack (6 jobs) ----
    WrepackJobs WJ;
    {
        int s = 0;
        for (int i = 0; i < 3; i++) {
            const int C = Cs[i];
            WJ.w[i * 2]      = (const float*)d_in[widx[i] + 0];
            WJ.wr[i * 2]     = wr1 + wroff[i];
            WJ.C[i * 2]      = C;
            WJ.start[i * 2]  = s;  s += C * C;
            WJ.w[i * 2 + 1]     = (const float*)d_in[widx[i] + 3];
            WJ.wr[i * 2 + 1]    = wr2 + wroff[i];
            WJ.C[i * 2 + 1]     = C;
            WJ.start[i * 2 + 1] = s;  s += C * C;
        }
        WJ.start[6] = s;
        wrepack_all_kernel<<<(s + 255) / 256, 256>>>(WJ);
    }

    // ---- batched pad+transpose (3 levels) ----
    PadJobs PJ;
    {
        int s = 0;
        for (int i = 0; i < 3; i++) {
            const int C = Cs[i], W = Ws[i];
            PJ.in[i] = (const float*)d_in[xin[i]];
            PJ.Xp[i] = xpad + xoff[i];
            PJ.C[i]  = C;  PJ.W[i] = W;
            PJ.start[i] = s;
            s += (W * W / 32) * (C / 32) * B;
        }
        PJ.start[3] = s;
        pad_all_kernel<<<s, dim3(32, 8)>>>(PJ);
    }

    // ---- batched conv GEMMs ----
    LevelParams L1[3], L2[3];
    int start = 0;
    for (int i = 0; i < 3; i++) {
        const int C = Cs[i], W = Ws[i], Wp = W + 2, Np = Wp * Wp;
        const int tiles = (Np + 127) / 128, cgrp = C / 128;
        L1[i] = { xpad + xoff[i], wr1 + wroff[i],
                  (const float*)d_in[widx[i] + 1], (const float*)d_in[widx[i] + 2],
                  (void*)(ypad + xoff[i]), C, W, Wp, Np, start, tiles, cgrp };
        L2[i] = { ypad + xoff[i], wr2 + wroff[i],
                  (const float*)d_in[widx[i] + 4], (const float*)d_in[widx[i] + 5],
                  (void*)(y2 + y2off[i]), C, W, Wp, Np, start, tiles, cgrp };
        start += tiles * cgrp * B;
    }
    conv_gemm_kernel<<<start, 256, CONV_SMEM>>>(L1[0], L1[1], L1[2], 0);
    conv_gemm_kernel<<<start, 256, CONV_SMEM>>>(L2[0], L2[1], L2[2], 1);

    // ---- batched decode (3 levels) ----
    DecJobs DJ;
    {
        int s = 0;
        // order p3 first (largest)
        const int ord[3] = {2, 1, 0};   // indices into the p5,p4,p3 tables
        for (int oi = 0; oi < 3; oi++) {
            int i = ord[oi];
            const int C = Cs[i], W = Ws[i];
            DJ.y2[oi] = y2 + y2off[i];
            DJ.wf[oi] = (const float*)d_in[widx[i] + 6];
            DJ.bf[oi] = (const float*)d_in[widx[i] + 7];
            DJ.C[oi] = C;  DJ.W[oi] = W;
            DJ.aoff[oi] = aoff[i];  DJ.stride[oi] = strd[i];
            DJ.start[oi] = s;
            s += (W * W / 8) * B;
        }
        DJ.start[3] = s;
        decode_all_kernel<<<s, 256>>>(DJ, out);
    }
}

// round 12
// speedup vs baseline: 1.0440x; 1.0440x over previous
#include <cuda_runtime.h>
#include <cuda_bf16.h>
#include <math.h>
#include <stdint.h>

// ===========================================================================
// YOLOv8 head via bf16 mma.sync implicit GEMM (shifted-GEMM conv).
//   conv3x3(pad1) == sum over 9 kernel offsets k of GEMM:
//      D[co, p] += W_k[co, ci] * Xpad[p + off_k, ci]
// R12: R10 structure (best: batched conv launches, per-level aux launches)
//      + y2 stored as bf16 (halves conv2-epilogue store + decode read traffic).
// ===========================================================================

#define ATOT 33600

// per-level xpad/ypad region offsets (halves)
#define OFF_P3 262144
#define OFF_P4 27398144
#define OFF_P5 41431040
#define XPAD_TOTAL 48918528

// per-level y2 offsets (bf16 elements)
#define Y2_P3 0
#define Y2_P4 26214400
#define Y2_P5 39321600
#define Y2_TOTAL 45875200

// per-level wrep offsets (halves): p5 first
#define WR_P5 0
#define WR_P4 2359296
#define WR_P3 2949120
#define WR_TOTAL 3096576

__device__ __align__(256) __nv_bfloat16 g_xpad[XPAD_TOTAL];
__device__ __align__(256) __nv_bfloat16 g_ypad[XPAD_TOTAL];
__device__ __align__(256) __nv_bfloat16 g_y2  [Y2_TOTAL];
__device__ __align__(256) __nv_bfloat16 g_wr1 [WR_TOTAL];
__device__ __align__(256) __nv_bfloat16 g_wr2 [WR_TOTAL];

struct LevelParams {
    const __nv_bfloat16* X;
    const __nv_bfloat16* Wr;
    const float* scale;
    const float* bias;
    void* Y;
    int C, W, Wp, Np;
    int start;      // first flat CTA index of this level
    int tiles;      // pixel tiles = ceil(Np/128)
    int cgrp;       // C / 128
};

__device__ __forceinline__ uint32_t smem_u32(const void* p) {
    return (uint32_t)__cvta_generic_to_shared(p);
}
__device__ __forceinline__ void cp_async16(uint32_t dst, const void* src) {
    asm volatile("cp.async.cg.shared.global [%0], [%1], 16;"
                 :: "r"(dst), "l"(__cvta_generic_to_global(src)) : "memory");
}
__device__ __forceinline__ void cp_commit() {
    asm volatile("cp.async.commit_group;" ::: "memory");
}
__device__ __forceinline__ void ldsm_x4(uint32_t& r0, uint32_t& r1,
                                        uint32_t& r2, uint32_t& r3, uint32_t a) {
    asm volatile("ldmatrix.sync.aligned.m8n8.x4.shared.b16 {%0,%1,%2,%3}, [%4];"
                 : "=r"(r0), "=r"(r1), "=r"(r2), "=r"(r3) : "r"(a));
}
__device__ __forceinline__ void mma_bf16(float& d0, float& d1, float& d2, float& d3,
                                         uint32_t a0, uint32_t a1, uint32_t a2, uint32_t a3,
                                         uint32_t b0, uint32_t b1) {
    asm volatile(
        "mma.sync.aligned.m16n8k16.row.col.f32.bf16.bf16.f32 "
        "{%0,%1,%2,%3}, {%4,%5,%6,%7}, {%8,%9}, {%0,%1,%2,%3};"
        : "+f"(d0), "+f"(d1), "+f"(d2), "+f"(d3)
        : "r"(a0), "r"(a1), "r"(a2), "r"(a3), "r"(b0), "r"(b1));
}

// ---------------------------------------------------------------------------
// weight repack: W(co,ci,3,3) fp32 -> Wrep[k][co][ci] bf16
// ---------------------------------------------------------------------------
__global__ void wrepack_kernel(const float* __restrict__ w,
                               __nv_bfloat16* __restrict__ wr, int C)
{
    int idx = blockIdx.x * blockDim.x + threadIdx.x;   // co*C + ci
    if (idx >= C * C) return;
#pragma unroll
    for (int k = 0; k < 9; k++)
        wr[(size_t)k * C * C + idx] = __float2bfloat16_rn(w[(size_t)idx * 9 + k]);
}

// ---------------------------------------------------------------------------
// pad+transpose: NCHW fp32 -> Xpad[n][p][ci] bf16 (interior pixels only)
// ---------------------------------------------------------------------------
__global__ void pad_transpose_kernel(const float* __restrict__ in,
                                     __nv_bfloat16* __restrict__ Xp,
                                     int C, int H, int W, int Wp, int Np)
{
    __shared__ float t[32][33];
    const int HW = H * W;
    const int q0 = blockIdx.x * 32;
    const int c0 = blockIdx.y * 32;
    const int n  = blockIdx.z;
    const int tx = threadIdx.x, ty = threadIdx.y;

    const float* inN = in + (size_t)n * C * HW;
#pragma unroll
    for (int j = 0; j < 4; j++) {
        int c = c0 + ty + j * 8;
        t[ty + j * 8][tx] = inN[(size_t)c * HW + q0 + tx];
    }
    __syncthreads();
    __nv_bfloat16* XpN = Xp + (size_t)n * Np * C;
#pragma unroll
    for (int j = 0; j < 4; j++) {
        int q = q0 + ty + j * 8;
        int py = q / W, px = q - py * W;
        int p = (py + 1) * Wp + px + 1;
        XpN[(size_t)p * C + c0 + tx] = __float2bfloat16_rn(t[tx][ty + j * 8]);
    }
}

// ---------------------------------------------------------------------------
// batched conv GEMM over 3 levels: D[128 co x 128 px] = sum Wrep_k * Xpad(+off)
// 8 warps (2M x 4N), warp tile 64x32, mma m16n8k16 bf16, K-chunk 64,
// 3-stage cp.async pipeline, ldmatrix fragments. Level from flat blockIdx.x.
// mode 0: bf16 padded [p][co]; mode 1: bf16 unpadded [q][co].
// ---------------------------------------------------------------------------
#define KS      72                      // halves per smem row (64 + 8 pad)
#define STAGEH  (2 * 128 * KS)          // halves per stage (A tile + B tile)
#define OSTRIDE 132

__global__ void __launch_bounds__(256, 2)
conv_gemm_kernel(LevelParams l0, LevelParams l1, LevelParams l2, int mode)
{
    extern __shared__ __nv_bfloat16 dsm[];   // 3 stages of [A(128xKS) | B(128xKS)]

    const int x = blockIdx.x;
    const LevelParams L = (x >= l2.start) ? l2 : ((x >= l1.start) ? l1 : l0);

    const int idx  = x - L.start;
    const int tile = idx % L.tiles;
    const int rest = idx / L.tiles;
    const int cog  = rest % L.cgrp;
    const int n    = rest / L.cgrp;

    const int C = L.C, W = L.W, Wp = L.Wp, Np = L.Np;
    const int p0  = tile * 128;
    const int co0 = cog * 128;

    const int tid    = threadIdx.x;
    const int lane   = tid & 31;
    const int wid    = tid >> 5;
    const int warp_m = wid >> 2;        // 0..1
    const int warp_n = wid & 3;         // 0..3

    const __nv_bfloat16* Ximg = L.X + (size_t)n * Np * C;
    const __nv_bfloat16* wrep = L.Wr;
    const int NC = 9 * (C >> 6);        // K-chunks of 64 ci

    float acc[4][4][4];
#pragma unroll
    for (int mi = 0; mi < 4; mi++)
#pragma unroll
        for (int ni = 0; ni < 4; ni++)
#pragma unroll
            for (int r = 0; r < 4; r++) acc[mi][ni][r] = 0.f;

    const uint32_t smem0 = smem_u32(dsm);

    auto load_chunk = [&](int c, int buf) {
        const int k   = c % 9;
        const int cic = c / 9;
        const int off = (k / 3 - 1) * Wp + (k % 3 - 1);
        const __nv_bfloat16* Asrc = wrep + ((size_t)k * C + co0) * C + cic * 64;
        const __nv_bfloat16* Bsrc = Ximg + (long long)(p0 + off) * C + cic * 64;
        const uint32_t sAb = smem0 + buf * (STAGEH * 2);
        const uint32_t sBb = sAb + 128 * KS * 2;
#pragma unroll
        for (int i = 0; i < 4; i++) {
            int e = tid + i * 256, r = e >> 3, f = e & 7;
            cp_async16(sAb + (r * KS + f * 8) * 2, Asrc + (size_t)r * C + f * 8);
            cp_async16(sBb + (r * KS + f * 8) * 2, Bsrc + (long long)r * C + f * 8);
        }
        cp_commit();
    };

    // per-thread ldmatrix byte offsets (stage-relative)
    uint32_t aOff[4], bOff[2];
#pragma unroll
    for (int mi = 0; mi < 4; mi++) {
        int row = warp_m * 64 + mi * 16 + (lane & 15);
        aOff[mi] = (uint32_t)((row * KS + ((lane >> 4) << 3)) * 2);
    }
#pragma unroll
    for (int np = 0; np < 2; np++) {
        int px = warp_n * 32 + np * 16 + ((lane >> 4) << 3) + (lane & 7);
        bOff[np] = (uint32_t)((px * KS + (((lane >> 3) & 1) << 3)) * 2) + 128 * KS * 2;
    }

    load_chunk(0, 0);
    if (NC > 1) load_chunk(1, 1);

    int buf = 0;
    for (int c = 0; c < NC; c++) {
        if (c + 1 < NC)
            asm volatile("cp.async.wait_group 1;" ::: "memory");
        else
            asm volatile("cp.async.wait_group 0;" ::: "memory");
        __syncthreads();

        if (c + 2 < NC) {
            int nb = buf + 2; if (nb >= 3) nb -= 3;
            load_chunk(c + 2, nb);
        }

        const uint32_t sbase = smem0 + buf * (STAGEH * 2);
#pragma unroll
        for (int ks = 0; ks < 4; ks++) {
            const uint32_t ko = ks * 32;    // 16 halves
            uint32_t af[4][4], bf[2][4];
#pragma unroll
            for (int mi = 0; mi < 4; mi++)
                ldsm_x4(af[mi][0], af[mi][1], af[mi][2], af[mi][3],
                        sbase + aOff[mi] + ko);
#pragma unroll
            for (int np = 0; np < 2; np++)
                ldsm_x4(bf[np][0], bf[np][1], bf[np][2], bf[np][3],
                        sbase + bOff[np] + ko);
#pragma unroll
            for (int mi = 0; mi < 4; mi++)
#pragma unroll
                for (int ni = 0; ni < 4; ni++)
                    mma_bf16(acc[mi][ni][0], acc[mi][ni][1], acc[mi][ni][2], acc[mi][ni][3],
                             af[mi][0], af[mi][1], af[mi][2], af[mi][3],
                             bf[ni >> 1][(ni & 1) * 2], bf[ni >> 1][(ni & 1) * 2 + 1]);
        }
        buf++; if (buf == 3) buf = 0;
    }
    __syncthreads();

    // ---- epilogue: BN+ReLU, stage [px][co] fp32 tile in smem ----
    float* st = (float*)dsm;
    {
        const int g  = lane >> 2;
        const int q2 = (lane & 3) << 1;
#pragma unroll
        for (int mi = 0; mi < 4; mi++) {
            const int col0 = warp_m * 64 + mi * 16 + g;
            const float s0 = __ldg(L.scale + co0 + col0),     b0 = __ldg(L.bias + co0 + col0);
            const float s1 = __ldg(L.scale + co0 + col0 + 8), b1 = __ldg(L.bias + co0 + col0 + 8);
#pragma unroll
            for (int ni = 0; ni < 4; ni++) {
                const int pxl = warp_n * 32 + ni * 8 + q2;
                st[pxl * OSTRIDE + col0]           = fmaxf(fmaf(acc[mi][ni][0], s0, b0), 0.f);
                st[(pxl + 1) * OSTRIDE + col0]     = fmaxf(fmaf(acc[mi][ni][1], s0, b0), 0.f);
                st[pxl * OSTRIDE + col0 + 8]       = fmaxf(fmaf(acc[mi][ni][2], s1, b1), 0.f);
                st[(pxl + 1) * OSTRIDE + col0 + 8] = fmaxf(fmaf(acc[mi][ni][3], s1, b1), 0.f);
            }
        }
    }
    __syncthreads();

#pragma unroll 1
    for (int i = 0; i < 16; i++) {
        int idx2 = tid + i * 256;
        int r = idx2 >> 5, f = idx2 & 31;
        int p = p0 + r;
        if (p < Np) {
            int py = p / Wp, px = p - py * Wp;
            if (py >= 1 && py <= W && px >= 1 && px <= W) {
                float4 v = *(const float4*)&st[r * OSTRIDE + f * 4];
                __nv_bfloat162 h0 = __floats2bfloat162_rn(v.x, v.y);
                __nv_bfloat162 h1 = __floats2bfloat162_rn(v.z, v.w);
                uint2 pk;
                pk.x = *reinterpret_cast<uint32_t*>(&h0);
                pk.y = *reinterpret_cast<uint32_t*>(&h1);
                if (mode == 0) {
                    __nv_bfloat16* Yb = (__nv_bfloat16*)L.Y + (size_t)n * Np * C;
                    *(uint2*)&Yb[(size_t)p * C + co0 + f * 4] = pk;
                } else {
                    __nv_bfloat16* Yb = (__nv_bfloat16*)L.Y + (size_t)n * (size_t)(W * W) * C;
                    *(uint2*)&Yb[((size_t)(py - 1) * W + (px - 1)) * C + co0 + f * 4] = pk;
                }
            }
        }
    }
}

// ---------------------------------------------------------------------------
// 1x1 conv (C->5) + decode + sigmoid. warp-per-pixel, y2 bf16 [n][q][C].
// ---------------------------------------------------------------------------
__global__ void __launch_bounds__(256)
conv1x1_decode_kernel(const __nv_bfloat16* __restrict__ y2,
                      const float* __restrict__ wf,
                      const float* __restrict__ bf,
                      float* __restrict__ out,
                      int C, int W, int HW, int aoff, float stride)
{
    __shared__ float s_wf[5 * 512];
    for (int t = threadIdx.x; t < 5 * C; t += 256) s_wf[t] = wf[t];
    __syncthreads();

    const int wid  = threadIdx.x >> 5;
    const int lane = threadIdx.x & 31;
    const int q = blockIdx.x * 8 + wid;
    const int n = blockIdx.y;
    if (q >= HW) return;

    const __nv_bfloat16* yq = y2 + ((size_t)n * HW + q) * C;
    float a[5] = {0.f, 0.f, 0.f, 0.f, 0.f};
    const int iters = C >> 7;
    for (int it = 0; it < iters; it++) {
        int cb = it * 128 + lane * 4;
        uint2 vp = *(const uint2*)(yq + cb);
        __nv_bfloat162 h0 = *reinterpret_cast<__nv_bfloat162*>(&vp.x);
        __nv_bfloat162 h1 = *reinterpret_cast<__nv_bfloat162*>(&vp.y);
        float2 f0 = __bfloat1622float2(h0);
        float2 f1 = __bfloat1622float2(h1);
#pragma unroll
        for (int j = 0; j < 5; j++) {
            const float* wj = s_wf + j * C + cb;
            a[j] += f0.x * wj[0] + f0.y * wj[1] + f1.x * wj[2] + f1.y * wj[3];
        }
    }
#pragma unroll
    for (int j = 0; j < 5; j++)
#pragma unroll
        for (int o = 16; o; o >>= 1)
            a[j] += __shfl_xor_sync(0xffffffffu, a[j], o);

    if (lane == 0) {
        float a0 = a[0] + bf[0], a1 = a[1] + bf[1], a2 = a[2] + bf[2];
        float a3 = a[3] + bf[3], a4 = a[4] + bf[4];
        int py = q / W, px = q - py * W;
        float ax = px + 0.5f, ay = py + 0.5f;
        float cx = (ax + 0.5f * (a2 - a0)) * stride;
        float cy = (ay + 0.5f * (a3 - a1)) * stride;
        float bw = (a2 + a0) * stride;
        float bh = (a3 + a1) * stride;
        float cls = 1.f / (1.f + expf(-a4));
        size_t base = (size_t)n * 5 * ATOT + (size_t)aoff + q;
        out[base]                    = cx;
        out[base + (size_t)ATOT]     = cy;
        out[base + 2 * (size_t)ATOT] = bw;
        out[base + 3 * (size_t)ATOT] = bh;
        out[base + 4 * (size_t)ATOT] = cls;
    }
}

// ---------------------------------------------------------------------------
// Host
// ---------------------------------------------------------------------------
#define CONV_SMEM (3 * STAGEH * 2)   // 110,592 B

extern "C" void kernel_launch(void* const* d_in, const int* in_sizes, int n_in,
                              void* d_out, int out_size)
{
    __nv_bfloat16 *xpad, *ypad, *wr1, *wr2, *y2;
    cudaGetSymbolAddress((void**)&xpad, g_xpad);
    cudaGetSymbolAddress((void**)&ypad, g_ypad);
    cudaGetSymbolAddress((void**)&y2,   g_y2);
    cudaGetSymbolAddress((void**)&wr1,  g_wr1);
    cudaGetSymbolAddress((void**)&wr2,  g_wr2);

    cudaFuncSetAttribute(conv_gemm_kernel,
                         cudaFuncAttributeMaxDynamicSharedMemorySize, CONV_SMEM);

    const int B = in_sizes[0] / (128 * 160 * 160);
    float* out = (float*)d_out;

    // level static tables: order p5, p4, p3 (longest conv CTAs first)
    const int   Cs[3]   = {512, 256, 128};
    const int   Ws[3]   = {40, 80, 160};
    const int   xin[3]  = {2, 1, 0};
    const int   widx[3] = {19, 11, 3};
    const int   xoff[3] = {OFF_P5, OFF_P4, OFF_P3};
    const int   y2off[3]= {Y2_P5, Y2_P4, Y2_P3};
    const int   wroff[3]= {WR_P5, WR_P4, WR_P3};
    const int   aoff[3] = {32000, 25600, 0};
    const float strd[3] = {32.f, 16.f, 8.f};

    LevelParams L1[3], L2[3];
    int start = 0;
    for (int i = 0; i < 3; i++) {
        const int C = Cs[i], W = Ws[i], Wp = W + 2, Np = Wp * Wp;
        const int tiles = (Np + 127) / 128, cgrp = C / 128;

        // weight repack (both convs)
        wrepack_kernel<<<(C * C + 255) / 256, 256>>>(
            (const float*)d_in[widx[i] + 0], wr1 + wroff[i], C);
        wrepack_kernel<<<(C * C + 255) / 256, 256>>>(
            (const float*)d_in[widx[i] + 3], wr2 + wroff[i], C);

        // pad+transpose input
        dim3 gp((W * W) / 32, C / 32, B);
        pad_transpose_kernel<<<gp, dim3(32, 8)>>>(
            (const float*)d_in[xin[i]], xpad + xoff[i], C, W, W, Wp, Np);

        L1[i] = { xpad + xoff[i], wr1 + wroff[i],
                  (const float*)d_in[widx[i] + 1], (const float*)d_in[widx[i] + 2],
                  (void*)(ypad + xoff[i]), C, W, Wp, Np, start, tiles, cgrp };
        L2[i] = { ypad + xoff[i], wr2 + wroff[i],
                  (const float*)d_in[widx[i] + 4], (const float*)d_in[widx[i] + 5],
                  (void*)(y2 + y2off[i]), C, W, Wp, Np, start, tiles, cgrp };
        start += tiles * cgrp * B;
    }

    // batched convs: one launch per conv index, all levels
    conv_gemm_kernel<<<start, 256, CONV_SMEM>>>(L1[0], L1[1], L1[2], 0);
    conv_gemm_kernel<<<start, 256, CONV_SMEM>>>(L2[0], L2[1], L2[2], 1);

    // decode per level
    for (int i = 0; i < 3; i++) {
        const int W = Ws[i], HW = W * W, C = Cs[i];
        dim3 gd((HW + 7) / 8, B);
        conv1x1_decode_kernel<<<gd, 256>>>(
            y2 + y2off[i], (const float*)d_in[widx[i] + 6],
            (const float*)d_in[widx[i] + 7], out, C, W, HW, aoff[i], strd[i]);
    }
}

// round 13
// speedup vs baseline: 1.0571x; 1.0125x over previous
#include <cuda_runtime.h>
#include <cuda_bf16.h>
#include <math.h>
#include <stdint.h>

// ===========================================================================
// YOLOv8 head via bf16 mma.sync implicit GEMM (shifted-GEMM conv).
//   conv3x3(pad1) == sum over 9 kernel offsets k of GEMM:
//      D[co, p] += W_k[co, ci] * Xpad[p + off_k, ci]
// R13: R12 structure (batched conv launches = best measured) + aux polish:
//      wrepack -> thread-per-output (coalesced writes, 9x parallelism),
//      pad_transpose -> 64-channel tiles, packed bf16x2 stores.
// ===========================================================================

#define ATOT 33600

// per-level xpad/ypad region offsets (halves)
#define OFF_P3 262144
#define OFF_P4 27398144
#define OFF_P5 41431040
#define XPAD_TOTAL 48918528

// per-level y2 offsets (bf16 elements)
#define Y2_P3 0
#define Y2_P4 26214400
#define Y2_P5 39321600
#define Y2_TOTAL 45875200

// per-level wrep offsets (halves): p5 first
#define WR_P5 0
#define WR_P4 2359296
#define WR_P3 2949120
#define WR_TOTAL 3096576

__device__ __align__(256) __nv_bfloat16 g_xpad[XPAD_TOTAL];
__device__ __align__(256) __nv_bfloat16 g_ypad[XPAD_TOTAL];
__device__ __align__(256) __nv_bfloat16 g_y2  [Y2_TOTAL];
__device__ __align__(256) __nv_bfloat16 g_wr1 [WR_TOTAL];
__device__ __align__(256) __nv_bfloat16 g_wr2 [WR_TOTAL];

struct LevelParams {
    const __nv_bfloat16* X;
    const __nv_bfloat16* Wr;
    const float* scale;
    const float* bias;
    void* Y;
    int C, W, Wp, Np;
    int start;      // first flat CTA index of this level
    int tiles;      // pixel tiles = ceil(Np/128)
    int cgrp;       // C / 128
};

__device__ __forceinline__ uint32_t smem_u32(const void* p) {
    return (uint32_t)__cvta_generic_to_shared(p);
}
__device__ __forceinline__ void cp_async16(uint32_t dst, const void* src) {
    asm volatile("cp.async.cg.shared.global [%0], [%1], 16;"
                 :: "r"(dst), "l"(__cvta_generic_to_global(src)) : "memory");
}
__device__ __forceinline__ void cp_commit() {
    asm volatile("cp.async.commit_group;" ::: "memory");
}
__device__ __forceinline__ void ldsm_x4(uint32_t& r0, uint32_t& r1,
                                        uint32_t& r2, uint32_t& r3, uint32_t a) {
    asm volatile("ldmatrix.sync.aligned.m8n8.x4.shared.b16 {%0,%1,%2,%3}, [%4];"
                 : "=r"(r0), "=r"(r1), "=r"(r2), "=r"(r3) : "r"(a));
}
__device__ __forceinline__ void mma_bf16(float& d0, float& d1, float& d2, float& d3,
                                         uint32_t a0, uint32_t a1, uint32_t a2, uint32_t a3,
                                         uint32_t b0, uint32_t b1) {
    asm volatile(
        "mma.sync.aligned.m16n8k16.row.col.f32.bf16.bf16.f32 "
        "{%0,%1,%2,%3}, {%4,%5,%6,%7}, {%8,%9}, {%0,%1,%2,%3};"
        : "+f"(d0), "+f"(d1), "+f"(d2), "+f"(d3)
        : "r"(a0), "r"(a1), "r"(a2), "r"(a3), "r"(b0), "r"(b1));
}

// ---------------------------------------------------------------------------
// weight repack: W(co,ci,3,3) fp32 -> Wrep[k][co][ci] bf16.
// One thread per OUTPUT element: coalesced writes, stride-9 reads (L1-absorbed).
// ---------------------------------------------------------------------------
__global__ void wrepack_kernel(const float* __restrict__ w,
                               __nv_bfloat16* __restrict__ wr, int C)
{
    int o = blockIdx.x * blockDim.x + threadIdx.x;   // k*C*C + e
    const int plane = C * C;
    if (o >= 9 * plane) return;
    int k = o / plane;
    int e = o - k * plane;
    wr[o] = __float2bfloat16_rn(w[(size_t)e * 9 + k]);
}

// ---------------------------------------------------------------------------
// pad+transpose: NCHW fp32 -> Xpad[n][p][ci] bf16 (interior pixels only).
// 64-channel x 32-pixel tiles; packed bf16x2 stores (4B per thread-store).
// ---------------------------------------------------------------------------
__global__ void pad_transpose_kernel(const float* __restrict__ in,
                                     __nv_bfloat16* __restrict__ Xp,
                                     int C, int H, int W, int Wp, int Np)
{
    __shared__ float t[64][33];
    const int HW = H * W;
    const int q0 = blockIdx.x * 32;
    const int c0 = blockIdx.y * 64;
    const int n  = blockIdx.z;
    const int tx = threadIdx.x, ty = threadIdx.y;

    const float* inN = in + (size_t)n * C * HW;
#pragma unroll
    for (int j = 0; j < 8; j++) {
        int cc = ty + j * 8;                       // 0..63
        t[cc][tx] = inN[(size_t)(c0 + cc) * HW + q0 + tx];
    }
    __syncthreads();

    __nv_bfloat16* XpN = Xp + (size_t)n * Np * C;
#pragma unroll
    for (int j = 0; j < 4; j++) {
        int qq = ty + j * 8;                       // 0..31
        int q  = q0 + qq;
        int py = q / W, px = q - py * W;
        int p  = (py + 1) * Wp + px + 1;
        __nv_bfloat162 h = __floats2bfloat162_rn(t[2 * tx][qq], t[2 * tx + 1][qq]);
        *(uint32_t*)&XpN[(size_t)p * C + c0 + 2 * tx] = *reinterpret_cast<uint32_t*>(&h);
    }
}

// ---------------------------------------------------------------------------
// batched conv GEMM over 3 levels: D[128 co x 128 px] = sum Wrep_k * Xpad(+off)
// 8 warps (2M x 4N), warp tile 64x32, mma m16n8k16 bf16, K-chunk 64,
// 3-stage cp.async pipeline, ldmatrix fragments. Level from flat blockIdx.x.
// mode 0: bf16 padded [p][co]; mode 1: bf16 unpadded [q][co].
// ---------------------------------------------------------------------------
#define KS      72                      // halves per smem row (64 + 8 pad)
#define STAGEH  (2 * 128 * KS)          // halves per stage (A tile + B tile)
#define OSTRIDE 132

__global__ void __launch_bounds__(256, 2)
conv_gemm_kernel(LevelParams l0, LevelParams l1, LevelParams l2, int mode)
{
    extern __shared__ __nv_bfloat16 dsm[];   // 3 stages of [A(128xKS) | B(128xKS)]

    const int x = blockIdx.x;
    const LevelParams L = (x >= l2.start) ? l2 : ((x >= l1.start) ? l1 : l0);

    const int idx  = x - L.start;
    const int tile = idx % L.tiles;
    const int rest = idx / L.tiles;
    const int cog  = rest % L.cgrp;
    const int n    = rest / L.cgrp;

    const int C = L.C, W = L.W, Wp = L.Wp, Np = L.Np;
    const int p0  = tile * 128;
    const int co0 = cog * 128;

    const int tid    = threadIdx.x;
    const int lane   = tid & 31;
    const int wid    = tid >> 5;
    const int warp_m = wid >> 2;        // 0..1
    const int warp_n = wid & 3;         // 0..3

    const __nv_bfloat16* Ximg = L.X + (size_t)n * Np * C;
    const __nv_bfloat16* wrep = L.Wr;
    const int NC = 9 * (C >> 6);        // K-chunks of 64 ci

    float acc[4][4][4];
#pragma unroll
    for (int mi = 0; mi < 4; mi++)
#pragma unroll
        for (int ni = 0; ni < 4; ni++)
#pragma unroll
            for (int r = 0; r < 4; r++) acc[mi][ni][r] = 0.f;

    const uint32_t smem0 = smem_u32(dsm);

    auto load_chunk = [&](int c, int buf) {
        const int k   = c % 9;
        const int cic = c / 9;
        const int off = (k / 3 - 1) * Wp + (k % 3 - 1);
        const __nv_bfloat16* Asrc = wrep + ((size_t)k * C + co0) * C + cic * 64;
        const __nv_bfloat16* Bsrc = Ximg + (long long)(p0 + off) * C + cic * 64;
        const uint32_t sAb = smem0 + buf * (STAGEH * 2);
        const uint32_t sBb = sAb + 128 * KS * 2;
#pragma unroll
        for (int i = 0; i < 4; i++) {
            int e = tid + i * 256, r = e >> 3, f = e & 7;
            cp_async16(sAb + (r * KS + f * 8) * 2, Asrc + (size_t)r * C + f * 8);
            cp_async16(sBb + (r * KS + f * 8) * 2, Bsrc + (long long)r * C + f * 8);
        }
        cp_commit();
    };

    // per-thread ldmatrix byte offsets (stage-relative)
    uint32_t aOff[4], bOff[2];
#pragma unroll
    for (int mi = 0; mi < 4; mi++) {
        int row = warp_m * 64 + mi * 16 + (lane & 15);
        aOff[mi] = (uint32_t)((row * KS + ((lane >> 4) << 3)) * 2);
    }
#pragma unroll
    for (int np = 0; np < 2; np++) {
        int px = warp_n * 32 + np * 16 + ((lane >> 4) << 3) + (lane & 7);
        bOff[np] = (uint32_t)((px * KS + (((lane >> 3) & 1) << 3)) * 2) + 128 * KS * 2;
    }

    load_chunk(0, 0);
    if (NC > 1) load_chunk(1, 1);

    int buf = 0;
    for (int c = 0; c < NC; c++) {
        if (c + 1 < NC)
            asm volatile("cp.async.wait_group 1;" ::: "memory");
        else
            asm volatile("cp.async.wait_group 0;" ::: "memory");
        __syncthreads();

        if (c + 2 < NC) {
            int nb = buf + 2; if (nb >= 3) nb -= 3;
            load_chunk(c + 2, nb);
        }

        const uint32_t sbase = smem0 + buf * (STAGEH * 2);
#pragma unroll
        for (int ks = 0; ks < 4; ks++) {
            const uint32_t ko = ks * 32;    // 16 halves
            uint32_t af[4][4], bf[2][4];
#pragma unroll
            for (int mi = 0; mi < 4; mi++)
                ldsm_x4(af[mi][0], af[mi][1], af[mi][2], af[mi][3],
                        sbase + aOff[mi] + ko);
#pragma unroll
            for (int np = 0; np < 2; np++)
                ldsm_x4(bf[np][0], bf[np][1], bf[np][2], bf[np][3],
                        sbase + bOff[np] + ko);
#pragma unroll
            for (int mi = 0; mi < 4; mi++)
#pragma unroll
                for (int ni = 0; ni < 4; ni++)
                    mma_bf16(acc[mi][ni][0], acc[mi][ni][1], acc[mi][ni][2], acc[mi][ni][3],
                             af[mi][0], af[mi][1], af[mi][2], af[mi][3],
                             bf[ni >> 1][(ni & 1) * 2], bf[ni >> 1][(ni & 1) * 2 + 1]);
        }
        buf++; if (buf == 3) buf = 0;
    }
    __syncthreads();

    // ---- epilogue: BN+ReLU, stage [px][co] fp32 tile in smem ----
    float* st = (float*)dsm;
    {
        const int g  = lane >> 2;
        const int q2 = (lane & 3) << 1;
#pragma unroll
        for (int mi = 0; mi < 4; mi++) {
            const int col0 = warp_m * 64 + mi * 16 + g;
            const float s0 = __ldg(L.scale + co0 + col0),     b0 = __ldg(L.bias + co0 + col0);
            const float s1 = __ldg(L.scale + co0 + col0 + 8), b1 = __ldg(L.bias + co0 + col0 + 8);
#pragma unroll
            for (int ni = 0; ni < 4; ni++) {
                const int pxl = warp_n * 32 + ni * 8 + q2;
                st[pxl * OSTRIDE + col0]           = fmaxf(fmaf(acc[mi][ni][0], s0, b0), 0.f);
                st[(pxl + 1) * OSTRIDE + col0]     = fmaxf(fmaf(acc[mi][ni][1], s0, b0), 0.f);
                st[pxl * OSTRIDE + col0 + 8]       = fmaxf(fmaf(acc[mi][ni][2], s1, b1), 0.f);
                st[(pxl + 1) * OSTRIDE + col0 + 8] = fmaxf(fmaf(acc[mi][ni][3], s1, b1), 0.f);
            }
        }
    }
    __syncthreads();

#pragma unroll 1
    for (int i = 0; i < 16; i++) {
        int idx2 = tid + i * 256;
        int r = idx2 >> 5, f = idx2 & 31;
        int p = p0 + r;
        if (p < Np) {
            int py = p / Wp, px = p - py * Wp;
            if (py >= 1 && py <= W && px >= 1 && px <= W) {
                float4 v = *(const float4*)&st[r * OSTRIDE + f * 4];
                __nv_bfloat162 h0 = __floats2bfloat162_rn(v.x, v.y);
                __nv_bfloat162 h1 = __floats2bfloat162_rn(v.z, v.w);
                uint2 pk;
                pk.x = *reinterpret_cast<uint32_t*>(&h0);
                pk.y = *reinterpret_cast<uint32_t*>(&h1);
                if (mode == 0) {
                    __nv_bfloat16* Yb = (__nv_bfloat16*)L.Y + (size_t)n * Np * C;
                    *(uint2*)&Yb[(size_t)p * C + co0 + f * 4] = pk;
                } else {
                    __nv_bfloat16* Yb = (__nv_bfloat16*)L.Y + (size_t)n * (size_t)(W * W) * C;
                    *(uint2*)&Yb[((size_t)(py - 1) * W + (px - 1)) * C + co0 + f * 4] = pk;
                }
            }
        }
    }
}

// ---------------------------------------------------------------------------
// 1x1 conv (C->5) + decode + sigmoid. warp-per-pixel, y2 bf16 [n][q][C].
// ---------------------------------------------------------------------------
__global__ void __launch_bounds__(256)
conv1x1_decode_kernel(const __nv_bfloat16* __restrict__ y2,
                      const float* __restrict__ wf,
                      const float* __restrict__ bf,
                      float* __restrict__ out,
                      int C, int W, int HW, int aoff, float stride)
{
    __shared__ float s_wf[5 * 512];
    for (int t = threadIdx.x; t < 5 * C; t += 256) s_wf[t] = wf[t];
    __syncthreads();

    const int wid  = threadIdx.x >> 5;
    const int lane = threadIdx.x & 31;
    const int q = blockIdx.x * 8 + wid;
    const int n = blockIdx.y;
    if (q >= HW) return;

    const __nv_bfloat16* yq = y2 + ((size_t)n * HW + q) * C;
    float a[5] = {0.f, 0.f, 0.f, 0.f, 0.f};
    const int iters = C >> 7;
    for (int it = 0; it < iters; it++) {
        int cb = it * 128 + lane * 4;
        uint2 vp = *(const uint2*)(yq + cb);
        __nv_bfloat162 h0 = *reinterpret_cast<__nv_bfloat162*>(&vp.x);
        __nv_bfloat162 h1 = *reinterpret_cast<__nv_bfloat162*>(&vp.y);
        float2 f0 = __bfloat1622float2(h0);
        float2 f1 = __bfloat1622float2(h1);
#pragma unroll
        for (int j = 0; j < 5; j++) {
            const float* wj = s_wf + j * C + cb;
            a[j] += f0.x * wj[0] + f0.y * wj[1] + f1.x * wj[2] + f1.y * wj[3];
        }
    }
#pragma unroll
    for (int j = 0; j < 5; j++)
#pragma unroll
        for (int o = 16; o; o >>= 1)
            a[j] += __shfl_xor_sync(0xffffffffu, a[j], o);

    if (lane == 0) {
        float a0 = a[0] + bf[0], a1 = a[1] + bf[1], a2 = a[2] + bf[2];
        float a3 = a[3] + bf[3], a4 = a[4] + bf[4];
        int py = q / W, px = q - py * W;
        float ax = px + 0.5f, ay = py + 0.5f;
        float cx = (ax + 0.5f * (a2 - a0)) * stride;
        float cy = (ay + 0.5f * (a3 - a1)) * stride;
        float bw = (a2 + a0) * stride;
        float bh = (a3 + a1) * stride;
        float cls = 1.f / (1.f + expf(-a4));
        size_t base = (size_t)n * 5 * ATOT + (size_t)aoff + q;
        out[base]                    = cx;
        out[base + (size_t)ATOT]     = cy;
        out[base + 2 * (size_t)ATOT] = bw;
        out[base + 3 * (size_t)ATOT] = bh;
        out[base + 4 * (size_t)ATOT] = cls;
    }
}

// ---------------------------------------------------------------------------
// Host
// ---------------------------------------------------------------------------
#define CONV_SMEM (3 * STAGEH * 2)   // 110,592 B

extern "C" void kernel_launch(void* const* d_in, const int* in_sizes, int n_in,
                              void* d_out, int out_size)
{
    __nv_bfloat16 *xpad, *ypad, *wr1, *wr2, *y2;
    cudaGetSymbolAddress((void**)&xpad, g_xpad);
    cudaGetSymbolAddress((void**)&ypad, g_ypad);
    cudaGetSymbolAddress((void**)&y2,   g_y2);
    cudaGetSymbolAddress((void**)&wr1,  g_wr1);
    cudaGetSymbolAddress((void**)&wr2,  g_wr2);

    cudaFuncSetAttribute(conv_gemm_kernel,
                         cudaFuncAttributeMaxDynamicSharedMemorySize, CONV_SMEM);

    const int B = in_sizes[0] / (128 * 160 * 160);
    float* out = (float*)d_out;

    // level static tables: order p5, p4, p3 (longest conv CTAs first)
    const int   Cs[3]   = {512, 256, 128};
    const int   Ws[3]   = {40, 80, 160};
    const int   xin[3]  = {2, 1, 0};
    const int   widx[3] = {19, 11, 3};
    const int   xoff[3] = {OFF_P5, OFF_P4, OFF_P3};
    const int   y2off[3]= {Y2_P5, Y2_P4, Y2_P3};
    const int   wroff[3]= {WR_P5, WR_P4, WR_P3};
    const int   aoff[3] = {32000, 25600, 0};
    const float strd[3] = {32.f, 16.f, 8.f};

    LevelParams L1[3], L2[3];
    int start = 0;
    for (int i = 0; i < 3; i++) {
        const int C = Cs[i], W = Ws[i], Wp = W + 2, Np = Wp * Wp;
        const int tiles = (Np + 127) / 128, cgrp = C / 128;

        // weight repack (both convs) — thread per output element
        const int wtot = 9 * C * C;
        wrepack_kernel<<<(wtot + 255) / 256, 256>>>(
            (const float*)d_in[widx[i] + 0], wr1 + wroff[i], C);
        wrepack_kernel<<<(wtot + 255) / 256, 256>>>(
            (const float*)d_in[widx[i] + 3], wr2 + wroff[i], C);

        // pad+transpose input — 64-channel tiles
        dim3 gp((W * W) / 32, C / 64, B);
        pad_transpose_kernel<<<gp, dim3(32, 8)>>>(
            (const float*)d_in[xin[i]], xpad + xoff[i], C, W, W, Wp, Np);

        L1[i] = { xpad + xoff[i], wr1 + wroff[i],
                  (const float*)d_in[widx[i] + 1], (const float*)d_in[widx[i] + 2],
                  (void*)(ypad + xoff[i]), C, W, Wp, Np, start, tiles, cgrp };
        L2[i] = { ypad + xoff[i], wr2 + wroff[i],
                  (const float*)d_in[widx[i] + 4], (const float*)d_in[widx[i] + 5],
                  (void*)(y2 + y2off[i]), C, W, Wp, Np, start, tiles, cgrp };
        start += tiles * cgrp * B;
    }

    // batched convs: one launch per conv index, all levels
    conv_gemm_kernel<<<start, 256, CONV_SMEM>>>(L1[0], L1[1], L1[2], 0);
    conv_gemm_kernel<<<start, 256, CONV_SMEM>>>(L2[0], L2[1], L2[2], 1);

    // decode per level
    for (int i = 0; i < 3; i++) {
        const int W = Ws[i], HW = W * W, C = Cs[i];
        dim3 gd((HW + 7) / 8, B);
        conv1x1_decode_kernel<<<gd, 256>>>(
            y2 + y2off[i], (const float*)d_in[widx[i] + 6],
            (const float*)d_in[widx[i] + 7], out, C, W, HW, aoff[i], strd[i]);
    }
}

// round 14
// speedup vs baseline: 1.0663x; 1.0088x over previous
#include <cuda_runtime.h>
#include <cuda_bf16.h>
#include <math.h>
#include <stdint.h>

// ===========================================================================
// YOLOv8 head via bf16 mma.sync implicit GEMM (shifted-GEMM conv).
//   conv3x3(pad1) == sum over 9 kernel offsets k of GEMM:
//      D[co, p] += W_k[co, ci] * Xpad[p + off_k, ci]
// R14: R13 kernels byte-identical + stream fork/join: aux pre-stage kernels
//      (pads, wrepacks) run concurrently on 3 streams; decode likewise.
//      Conv launches (the measured floor) unchanged.
// ===========================================================================

#define ATOT 33600

// per-level xpad/ypad region offsets (halves)
#define OFF_P3 262144
#define OFF_P4 27398144
#define OFF_P5 41431040
#define XPAD_TOTAL 48918528

// per-level y2 offsets (bf16 elements)
#define Y2_P3 0
#define Y2_P4 26214400
#define Y2_P5 39321600
#define Y2_TOTAL 45875200

// per-level wrep offsets (halves): p5 first
#define WR_P5 0
#define WR_P4 2359296
#define WR_P3 2949120
#define WR_TOTAL 3096576

__device__ __align__(256) __nv_bfloat16 g_xpad[XPAD_TOTAL];
__device__ __align__(256) __nv_bfloat16 g_ypad[XPAD_TOTAL];
__device__ __align__(256) __nv_bfloat16 g_y2  [Y2_TOTAL];
__device__ __align__(256) __nv_bfloat16 g_wr1 [WR_TOTAL];
__device__ __align__(256) __nv_bfloat16 g_wr2 [WR_TOTAL];

struct LevelParams {
    const __nv_bfloat16* X;
    const __nv_bfloat16* Wr;
    const float* scale;
    const float* bias;
    void* Y;
    int C, W, Wp, Np;
    int start;      // first flat CTA index of this level
    int tiles;      // pixel tiles = ceil(Np/128)
    int cgrp;       // C / 128
};

__device__ __forceinline__ uint32_t smem_u32(const void* p) {
    return (uint32_t)__cvta_generic_to_shared(p);
}
__device__ __forceinline__ void cp_async16(uint32_t dst, const void* src) {
    asm volatile("cp.async.cg.shared.global [%0], [%1], 16;"
                 :: "r"(dst), "l"(__cvta_generic_to_global(src)) : "memory");
}
__device__ __forceinline__ void cp_commit() {
    asm volatile("cp.async.commit_group;" ::: "memory");
}
__device__ __forceinline__ void ldsm_x4(uint32_t& r0, uint32_t& r1,
                                        uint32_t& r2, uint32_t& r3, uint32_t a) {
    asm volatile("ldmatrix.sync.aligned.m8n8.x4.shared.b16 {%0,%1,%2,%3}, [%4];"
                 : "=r"(r0), "=r"(r1), "=r"(r2), "=r"(r3) : "r"(a));
}
__device__ __forceinline__ void mma_bf16(float& d0, float& d1, float& d2, float& d3,
                                         uint32_t a0, uint32_t a1, uint32_t a2, uint32_t a3,
                                         uint32_t b0, uint32_t b1) {
    asm volatile(
        "mma.sync.aligned.m16n8k16.row.col.f32.bf16.bf16.f32 "
        "{%0,%1,%2,%3}, {%4,%5,%6,%7}, {%8,%9}, {%0,%1,%2,%3};"
        : "+f"(d0), "+f"(d1), "+f"(d2), "+f"(d3)
        : "r"(a0), "r"(a1), "r"(a2), "r"(a3), "r"(b0), "r"(b1));
}

// ---------------------------------------------------------------------------
// weight repack: W(co,ci,3,3) fp32 -> Wrep[k][co][ci] bf16.
// One thread per OUTPUT element: coalesced writes, stride-9 reads (L1-absorbed).
// ---------------------------------------------------------------------------
__global__ void wrepack_kernel(const float* __restrict__ w,
                               __nv_bfloat16* __restrict__ wr, int C)
{
    int o = blockIdx.x * blockDim.x + threadIdx.x;   // k*C*C + e
    const int plane = C * C;
    if (o >= 9 * plane) return;
    int k = o / plane;
    int e = o - k * plane;
    wr[o] = __float2bfloat16_rn(w[(size_t)e * 9 + k]);
}

// ---------------------------------------------------------------------------
// pad+transpose: NCHW fp32 -> Xpad[n][p][ci] bf16 (interior pixels only).
// 64-channel x 32-pixel tiles; packed bf16x2 stores (4B per thread-store).
// ---------------------------------------------------------------------------
__global__ void pad_transpose_kernel(const float* __restrict__ in,
                                     __nv_bfloat16* __restrict__ Xp,
                                     int C, int H, int W, int Wp, int Np)
{
    __shared__ float t[64][33];
    const int HW = H * W;
    const int q0 = blockIdx.x * 32;
    const int c0 = blockIdx.y * 64;
    const int n  = blockIdx.z;
    const int tx = threadIdx.x, ty = threadIdx.y;

    const float* inN = in + (size_t)n * C * HW;
#pragma unroll
    for (int j = 0; j < 8; j++) {
        int cc = ty + j * 8;                       // 0..63
        t[cc][tx] = inN[(size_t)(c0 + cc) * HW + q0 + tx];
    }
    __syncthreads();

    __nv_bfloat16* XpN = Xp + (size_t)n * Np * C;
#pragma unroll
    for (int j = 0; j < 4; j++) {
        int qq = ty + j * 8;                       // 0..31
        int q  = q0 + qq;
        int py = q / W, px = q - py * W;
        int p  = (py + 1) * Wp + px + 1;
        __nv_bfloat162 h = __floats2bfloat162_rn(t[2 * tx][qq], t[2 * tx + 1][qq]);
        *(uint32_t*)&XpN[(size_t)p * C + c0 + 2 * tx] = *reinterpret_cast<uint32_t*>(&h);
    }
}

// ---------------------------------------------------------------------------
// batched conv GEMM over 3 levels: D[128 co x 128 px] = sum Wrep_k * Xpad(+off)
// 8 warps (2M x 4N), warp tile 64x32, mma m16n8k16 bf16, K-chunk 64,
// 3-stage cp.async pipeline, ldmatrix fragments. Level from flat blockIdx.x.
// mode 0: bf16 padded [p][co]; mode 1: bf16 unpadded [q][co].
// ---------------------------------------------------------------------------
#define KS      72                      // halves per smem row (64 + 8 pad)
#define STAGEH  (2 * 128 * KS)          // halves per stage (A tile + B tile)
#define OSTRIDE 132

__global__ void __launch_bounds__(256, 2)
conv_gemm_kernel(LevelParams l0, LevelParams l1, LevelParams l2, int mode)
{
    extern __shared__ __nv_bfloat16 dsm[];   // 3 stages of [A(128xKS) | B(128xKS)]

    const int x = blockIdx.x;
    const LevelParams L = (x >= l2.start) ? l2 : ((x >= l1.start) ? l1 : l0);

    const int idx  = x - L.start;
    const int tile = idx % L.tiles;
    const int rest = idx / L.tiles;
    const int cog  = rest % L.cgrp;
    const int n    = rest / L.cgrp;

    const int C = L.C, W = L.W, Wp = L.Wp, Np = L.Np;
    const int p0  = tile * 128;
    const int co0 = cog * 128;

    const int tid    = threadIdx.x;
    const int lane   = tid & 31;
    const int wid    = tid >> 5;
    const int warp_m = wid >> 2;        // 0..1
    const int warp_n = wid & 3;         // 0..3

    const __nv_bfloat16* Ximg = L.X + (size_t)n * Np * C;
    const __nv_bfloat16* wrep = L.Wr;
    const int NC = 9 * (C >> 6);        // K-chunks of 64 ci

    float acc[4][4][4];
#pragma unroll
    for (int mi = 0; mi < 4; mi++)
#pragma unroll
        for (int ni = 0; ni < 4; ni++)
#pragma unroll
            for (int r = 0; r < 4; r++) acc[mi][ni][r] = 0.f;

    const uint32_t smem0 = smem_u32(dsm);

    auto load_chunk = [&](int c, int buf) {
        const int k   = c % 9;
        const int cic = c / 9;
        const int off = (k / 3 - 1) * Wp + (k % 3 - 1);
        const __nv_bfloat16* Asrc = wrep + ((size_t)k * C + co0) * C + cic * 64;
        const __nv_bfloat16* Bsrc = Ximg + (long long)(p0 + off) * C + cic * 64;
        const uint32_t sAb = smem0 + buf * (STAGEH * 2);
        const uint32_t sBb = sAb + 128 * KS * 2;
#pragma unroll
        for (int i = 0; i < 4; i++) {
            int e = tid + i * 256, r = e >> 3, f = e & 7;
            cp_async16(sAb + (r * KS + f * 8) * 2, Asrc + (size_t)r * C + f * 8);
            cp_async16(sBb + (r * KS + f * 8) * 2, Bsrc + (long long)r * C + f * 8);
        }
        cp_commit();
    };

    // per-thread ldmatrix byte offsets (stage-relative)
    uint32_t aOff[4], bOff[2];
#pragma unroll
    for (int mi = 0; mi < 4; mi++) {
        int row = warp_m * 64 + mi * 16 + (lane & 15);
        aOff[mi] = (uint32_t)((row * KS + ((lane >> 4) << 3)) * 2);
    }
#pragma unroll
    for (int np = 0; np < 2; np++) {
        int px = warp_n * 32 + np * 16 + ((lane >> 4) << 3) + (lane & 7);
        bOff[np] = (uint32_t)((px * KS + (((lane >> 3) & 1) << 3)) * 2) + 128 * KS * 2;
    }

    load_chunk(0, 0);
    if (NC > 1) load_chunk(1, 1);

    int buf = 0;
    for (int c = 0; c < NC; c++) {
        if (c + 1 < NC)
            asm volatile("cp.async.wait_group 1;" ::: "memory");
        else
            asm volatile("cp.async.wait_group 0;" ::: "memory");
        __syncthreads();

        if (c + 2 < NC) {
            int nb = buf + 2; if (nb >= 3) nb -= 3;
            load_chunk(c + 2, nb);
        }

        const uint32_t sbase = smem0 + buf * (STAGEH * 2);
#pragma unroll
        for (int ks = 0; ks < 4; ks++) {
            const uint32_t ko = ks * 32;    // 16 halves
            uint32_t af[4][4], bf[2][4];
#pragma unroll
            for (int mi = 0; mi < 4; mi++)
                ldsm_x4(af[mi][0], af[mi][1], af[mi][2], af[mi][3],
                        sbase + aOff[mi] + ko);
#pragma unroll
            for (int np = 0; np < 2; np++)
                ldsm_x4(bf[np][0], bf[np][1], bf[np][2], bf[np][3],
                        sbase + bOff[np] + ko);
#pragma unroll
            for (int mi = 0; mi < 4; mi++)
#pragma unroll
                for (int ni = 0; ni < 4; ni++)
                    mma_bf16(acc[mi][ni][0], acc[mi][ni][1], acc[mi][ni][2], acc[mi][ni][3],
                             af[mi][0], af[mi][1], af[mi][2], af[mi][3],
                             bf[ni >> 1][(ni & 1) * 2], bf[ni >> 1][(ni & 1) * 2 + 1]);
        }
        buf++; if (buf == 3) buf = 0;
    }
    __syncthreads();

    // ---- epilogue: BN+ReLU, stage [px][co] fp32 tile in smem ----
    float* st = (float*)dsm;
    {
        const int g  = lane >> 2;
        const int q2 = (lane & 3) << 1;
#pragma unroll
        for (int mi = 0; mi < 4; mi++) {
            const int col0 = warp_m * 64 + mi * 16 + g;
            const float s0 = __ldg(L.scale + co0 + col0),     b0 = __ldg(L.bias + co0 + col0);
            const float s1 = __ldg(L.scale + co0 + col0 + 8), b1 = __ldg(L.bias + co0 + col0 + 8);
#pragma unroll
            for (int ni = 0; ni < 4; ni++) {
                const int pxl = warp_n * 32 + ni * 8 + q2;
                st[pxl * OSTRIDE + col0]           = fmaxf(fmaf(acc[mi][ni][0], s0, b0), 0.f);
                st[(pxl + 1) * OSTRIDE + col0]     = fmaxf(fmaf(acc[mi][ni][1], s0, b0), 0.f);
                st[pxl * OSTRIDE + col0 + 8]       = fmaxf(fmaf(acc[mi][ni][2], s1, b1), 0.f);
                st[(pxl + 1) * OSTRIDE + col0 + 8] = fmaxf(fmaf(acc[mi][ni][3], s1, b1), 0.f);
            }
        }
    }
    __syncthreads();

#pragma unroll 1
    for (int i = 0; i < 16; i++) {
        int idx2 = tid + i * 256;
        int r = idx2 >> 5, f = idx2 & 31;
        int p = p0 + r;
        if (p < Np) {
            int py = p / Wp, px = p - py * Wp;
            if (py >= 1 && py <= W && px >= 1 && px <= W) {
                float4 v = *(const float4*)&st[r * OSTRIDE + f * 4];
                __nv_bfloat162 h0 = __floats2bfloat162_rn(v.x, v.y);
                __nv_bfloat162 h1 = __floats2bfloat162_rn(v.z, v.w);
                uint2 pk;
                pk.x = *reinterpret_cast<uint32_t*>(&h0);
                pk.y = *reinterpret_cast<uint32_t*>(&h1);
                if (mode == 0) {
                    __nv_bfloat16* Yb = (__nv_bfloat16*)L.Y + (size_t)n * Np * C;
                    *(uint2*)&Yb[(size_t)p * C + co0 + f * 4] = pk;
                } else {
                    __nv_bfloat16* Yb = (__nv_bfloat16*)L.Y + (size_t)n * (size_t)(W * W) * C;
                    *(uint2*)&Yb[((size_t)(py - 1) * W + (px - 1)) * C + co0 + f * 4] = pk;
                }
            }
        }
    }
}

// ---------------------------------------------------------------------------
// 1x1 conv (C->5) + decode + sigmoid. warp-per-pixel, y2 bf16 [n][q][C].
// ---------------------------------------------------------------------------
__global__ void __launch_bounds__(256)
conv1x1_decode_kernel(const __nv_bfloat16* __restrict__ y2,
                      const float* __restrict__ wf,
                      const float* __restrict__ bf,
                      float* __restrict__ out,
                      int C, int W, int HW, int aoff, float stride)
{
    __shared__ float s_wf[5 * 512];
    for (int t = threadIdx.x; t < 5 * C; t += 256) s_wf[t] = wf[t];
    __syncthreads();

    const int wid  = threadIdx.x >> 5;
    const int lane = threadIdx.x & 31;
    const int q = blockIdx.x * 8 + wid;
    const int n = blockIdx.y;
    if (q >= HW) return;

    const __nv_bfloat16* yq = y2 + ((size_t)n * HW + q) * C;
    float a[5] = {0.f, 0.f, 0.f, 0.f, 0.f};
    const int iters = C >> 7;
    for (int it = 0; it < iters; it++) {
        int cb = it * 128 + lane * 4;
        uint2 vp = *(const uint2*)(yq + cb);
        __nv_bfloat162 h0 = *reinterpret_cast<__nv_bfloat162*>(&vp.x);
        __nv_bfloat162 h1 = *reinterpret_cast<__nv_bfloat162*>(&vp.y);
        float2 f0 = __bfloat1622float2(h0);
        float2 f1 = __bfloat1622float2(h1);
#pragma unroll
        for (int j = 0; j < 5; j++) {
            const float* wj = s_wf + j * C + cb;
            a[j] += f0.x * wj[0] + f0.y * wj[1] + f1.x * wj[2] + f1.y * wj[3];
        }
    }
#pragma unroll
    for (int j = 0; j < 5; j++)
#pragma unroll
        for (int o = 16; o; o >>= 1)
            a[j] += __shfl_xor_sync(0xffffffffu, a[j], o);

    if (lane == 0) {
        float a0 = a[0] + bf[0], a1 = a[1] + bf[1], a2 = a[2] + bf[2];
        float a3 = a[3] + bf[3], a4 = a[4] + bf[4];
        int py = q / W, px = q - py * W;
        float ax = px + 0.5f, ay = py + 0.5f;
        float cx = (ax + 0.5f * (a2 - a0)) * stride;
        float cy = (ay + 0.5f * (a3 - a1)) * stride;
        float bw = (a2 + a0) * stride;
        float bh = (a3 + a1) * stride;
        float cls = 1.f / (1.f + expf(-a4));
        size_t base = (size_t)n * 5 * ATOT + (size_t)aoff + q;
        out[base]                    = cx;
        out[base + (size_t)ATOT]     = cy;
        out[base + 2 * (size_t)ATOT] = bw;
        out[base + 3 * (size_t)ATOT] = bh;
        out[base + 4 * (size_t)ATOT] = cls;
    }
}

// ---------------------------------------------------------------------------
// Host
// ---------------------------------------------------------------------------
#define CONV_SMEM (3 * STAGEH * 2)   // 110,592 B

extern "C" void kernel_launch(void* const* d_in, const int* in_sizes, int n_in,
                              void* d_out, int out_size)
{
    // lazy one-time resource init (streams/events created on the correctness
    // run, before graph capture; reused as-is during capture — the captured
    // WORK is identical on every call)
    static cudaStream_t s1 = nullptr, s2 = nullptr;
    static cudaEvent_t evr = nullptr, ev1 = nullptr, ev2 = nullptr,
                       evc = nullptr, ed1 = nullptr, ed2 = nullptr;
    if (!s1) {
        cudaStreamCreateWithFlags(&s1, cudaStreamNonBlocking);
        cudaStreamCreateWithFlags(&s2, cudaStreamNonBlocking);
        cudaEventCreateWithFlags(&evr, cudaEventDisableTiming);
        cudaEventCreateWithFlags(&ev1, cudaEventDisableTiming);
        cudaEventCreateWithFlags(&ev2, cudaEventDisableTiming);
        cudaEventCreateWithFlags(&evc, cudaEventDisableTiming);
        cudaEventCreateWithFlags(&ed1, cudaEventDisableTiming);
        cudaEventCreateWithFlags(&ed2, cudaEventDisableTiming);
        cudaFuncSetAttribute(conv_gemm_kernel,
                             cudaFuncAttributeMaxDynamicSharedMemorySize, CONV_SMEM);
    }

    __nv_bfloat16 *xpad, *ypad, *wr1, *wr2, *y2;
    cudaGetSymbolAddress((void**)&xpad, g_xpad);
    cudaGetSymbolAddress((void**)&ypad, g_ypad);
    cudaGetSymbolAddress((void**)&y2,   g_y2);
    cudaGetSymbolAddress((void**)&wr1,  g_wr1);
    cudaGetSymbolAddress((void**)&wr2,  g_wr2);

    const int B = in_sizes[0] / (128 * 160 * 160);
    float* out = (float*)d_out;

    // level static tables: order p5, p4, p3 (longest conv CTAs first)
    const int   Cs[3]   = {512, 256, 128};
    const int   Ws[3]   = {40, 80, 160};
    const int   xin[3]  = {2, 1, 0};
    const int   widx[3] = {19, 11, 3};
    const int   xoff[3] = {OFF_P5, OFF_P4, OFF_P3};
    const int   y2off[3]= {Y2_P5, Y2_P4, Y2_P3};
    const int   wroff[3]= {WR_P5, WR_P4, WR_P3};
    const int   aoff[3] = {32000, 25600, 0};
    const float strd[3] = {32.f, 16.f, 8.f};

    // ---- fork: aux pre-stage on 3 streams ----
    cudaEventRecord(evr, 0);
    cudaStreamWaitEvent(s1, evr, 0);
    cudaStreamWaitEvent(s2, evr, 0);

    LevelParams L1[3], L2[3];
    int start = 0;
    for (int i = 0; i < 3; i++) {
        const int C = Cs[i], W = Ws[i], Wp = W + 2, Np = Wp * Wp;
        const int tiles = (Np + 127) / 128, cgrp = C / 128;

        // weight repack on default stream (tiny)
        const int wtot = 9 * C * C;
        wrepack_kernel<<<(wtot + 255) / 256, 256>>>(
            (const float*)d_in[widx[i] + 0], wr1 + wroff[i], C);
        wrepack_kernel<<<(wtot + 255) / 256, 256>>>(
            (const float*)d_in[widx[i] + 3], wr2 + wroff[i], C);

        // pad+transpose: p3 (largest, i==2) alone on s1; p5+p4 on s2
        dim3 gp((W * W) / 32, C / 64, B);
        cudaStream_t ps = (i == 2) ? s1 : s2;
        pad_transpose_kernel<<<gp, dim3(32, 8), 0, ps>>>(
            (const float*)d_in[xin[i]], xpad + xoff[i], C, W, W, Wp, Np);

        L1[i] = { xpad + xoff[i], wr1 + wroff[i],
                  (const float*)d_in[widx[i] + 1], (const float*)d_in[widx[i] + 2],
                  (void*)(ypad + xoff[i]), C, W, Wp, Np, start, tiles, cgrp };
        L2[i] = { ypad + xoff[i], wr2 + wroff[i],
                  (const float*)d_in[widx[i] + 4], (const float*)d_in[widx[i] + 5],
                  (void*)(y2 + y2off[i]), C, W, Wp, Np, start, tiles, cgrp };
        start += tiles * cgrp * B;
    }

    // ---- join ----
    cudaEventRecord(ev1, s1);
    cudaEventRecord(ev2, s2);
    cudaStreamWaitEvent(0, ev1, 0);
    cudaStreamWaitEvent(0, ev2, 0);

    // batched convs: one launch per conv index, all levels
    conv_gemm_kernel<<<start, 256, CONV_SMEM>>>(L1[0], L1[1], L1[2], 0);
    conv_gemm_kernel<<<start, 256, CONV_SMEM>>>(L2[0], L2[1], L2[2], 1);

    // ---- fork: decode per level on 3 streams ----
    cudaEventRecord(evc, 0);
    cudaStreamWaitEvent(s1, evc, 0);
    cudaStreamWaitEvent(s2, evc, 0);
    for (int i = 0; i < 3; i++) {
        const int W = Ws[i], HW = W * W, C = Cs[i];
        dim3 gd((HW + 7) / 8, B);
        cudaStream_t ds = (i == 2) ? (cudaStream_t)0 : (i == 1 ? s1 : s2);
        conv1x1_decode_kernel<<<gd, 256, 0, ds>>>(
            y2 + y2off[i], (const float*)d_in[widx[i] + 6],
            (const float*)d_in[widx[i] + 7], out, C, W, HW, aoff[i], strd[i]);
    }
    // ---- join back to the captured origin stream ----
    cudaEventRecord(ed1, s1);
    cudaEventRecord(ed2, s2);
    cudaStreamWaitEvent(0, ed1, 0);
    cudaStreamWaitEvent(0, ed2, 0);
}

// round 15
// speedup vs baseline: 1.0891x; 1.0214x over previous
#include <cuda_runtime.h>
#include <cuda_bf16.h>
#include <math.h>
#include <stdint.h>
#include <limits.h>

// ===========================================================================
// YOLOv8 head via bf16 mma.sync implicit GEMM (shifted-GEMM conv).
//   conv3x3(pad1) == sum over 9 kernel offsets k of GEMM:
//      D[co, p] += W_k[co, ci] * Xpad[p + off_k, ci]
// R15: per-level dependency chains on 3 concurrent streams (no global joins):
//      each level runs wrepack -> pad -> conv1 -> conv2 -> decode on its own
//      stream; cross-level tails/aux overlap. Kernels byte-identical to R14.
// ===========================================================================

#define ATOT 33600

// per-level xpad/ypad region offsets (halves)
#define OFF_P3 262144
#define OFF_P4 27398144
#define OFF_P5 41431040
#define XPAD_TOTAL 48918528

// per-level y2 offsets (bf16 elements)
#define Y2_P3 0
#define Y2_P4 26214400
#define Y2_P5 39321600
#define Y2_TOTAL 45875200

// per-level wrep offsets (halves): p5 first
#define WR_P5 0
#define WR_P4 2359296
#define WR_P3 2949120
#define WR_TOTAL 3096576

__device__ __align__(256) __nv_bfloat16 g_xpad[XPAD_TOTAL];
__device__ __align__(256) __nv_bfloat16 g_ypad[XPAD_TOTAL];
__device__ __align__(256) __nv_bfloat16 g_y2  [Y2_TOTAL];
__device__ __align__(256) __nv_bfloat16 g_wr1 [WR_TOTAL];
__device__ __align__(256) __nv_bfloat16 g_wr2 [WR_TOTAL];

struct LevelParams {
    const __nv_bfloat16* X;
    const __nv_bfloat16* Wr;
    const float* scale;
    const float* bias;
    void* Y;
    int C, W, Wp, Np;
    int start;      // first flat CTA index of this level
    int tiles;      // pixel tiles = ceil(Np/128)
    int cgrp;       // C / 128
};

__device__ __forceinline__ uint32_t smem_u32(const void* p) {
    return (uint32_t)__cvta_generic_to_shared(p);
}
__device__ __forceinline__ void cp_async16(uint32_t dst, const void* src) {
    asm volatile("cp.async.cg.shared.global [%0], [%1], 16;"
                 :: "r"(dst), "l"(__cvta_generic_to_global(src)) : "memory");
}
__device__ __forceinline__ void cp_commit() {
    asm volatile("cp.async.commit_group;" ::: "memory");
}
__device__ __forceinline__ void ldsm_x4(uint32_t& r0, uint32_t& r1,
                                        uint32_t& r2, uint32_t& r3, uint32_t a) {
    asm volatile("ldmatrix.sync.aligned.m8n8.x4.shared.b16 {%0,%1,%2,%3}, [%4];"
                 : "=r"(r0), "=r"(r1), "=r"(r2), "=r"(r3) : "r"(a));
}
__device__ __forceinline__ void mma_bf16(float& d0, float& d1, float& d2, float& d3,
                                         uint32_t a0, uint32_t a1, uint32_t a2, uint32_t a3,
                                         uint32_t b0, uint32_t b1) {
    asm volatile(
        "mma.sync.aligned.m16n8k16.row.col.f32.bf16.bf16.f32 "
        "{%0,%1,%2,%3}, {%4,%5,%6,%7}, {%8,%9}, {%0,%1,%2,%3};"
        : "+f"(d0), "+f"(d1), "+f"(d2), "+f"(d3)
        : "r"(a0), "r"(a1), "r"(a2), "r"(a3), "r"(b0), "r"(b1));
}

// ---------------------------------------------------------------------------
// weight repack: W(co,ci,3,3) fp32 -> Wrep[k][co][ci] bf16.
// One thread per OUTPUT element: coalesced writes, stride-9 reads (L1-absorbed).
// ---------------------------------------------------------------------------
__global__ void wrepack_kernel(const float* __restrict__ w,
                               __nv_bfloat16* __restrict__ wr, int C)
{
    int o = blockIdx.x * blockDim.x + threadIdx.x;   // k*C*C + e
    const int plane = C * C;
    if (o >= 9 * plane) return;
    int k = o / plane;
    int e = o - k * plane;
    wr[o] = __float2bfloat16_rn(w[(size_t)e * 9 + k]);
}

// ---------------------------------------------------------------------------
// pad+transpose: NCHW fp32 -> Xpad[n][p][ci] bf16 (interior pixels only).
// 64-channel x 32-pixel tiles; packed bf16x2 stores (4B per thread-store).
// ---------------------------------------------------------------------------
__global__ void pad_transpose_kernel(const float* __restrict__ in,
                                     __nv_bfloat16* __restrict__ Xp,
                                     int C, int H, int W, int Wp, int Np)
{
    __shared__ float t[64][33];
    const int HW = H * W;
    const int q0 = blockIdx.x * 32;
    const int c0 = blockIdx.y * 64;
    const int n  = blockIdx.z;
    const int tx = threadIdx.x, ty = threadIdx.y;

    const float* inN = in + (size_t)n * C * HW;
#pragma unroll
    for (int j = 0; j < 8; j++) {
        int cc = ty + j * 8;                       // 0..63
        t[cc][tx] = inN[(size_t)(c0 + cc) * HW + q0 + tx];
    }
    __syncthreads();

    __nv_bfloat16* XpN = Xp + (size_t)n * Np * C;
#pragma unroll
    for (int j = 0; j < 4; j++) {
        int qq = ty + j * 8;                       // 0..31
        int q  = q0 + qq;
        int py = q / W, px = q - py * W;
        int p  = (py + 1) * Wp + px + 1;
        __nv_bfloat162 h = __floats2bfloat162_rn(t[2 * tx][qq], t[2 * tx + 1][qq]);
        *(uint32_t*)&XpN[(size_t)p * C + c0 + 2 * tx] = *reinterpret_cast<uint32_t*>(&h);
    }
}

// ---------------------------------------------------------------------------
// conv GEMM (level selected by flat blockIdx.x; single-level use passes
// INT_MAX starts for l1/l2): D[128 co x 128 px] = sum Wrep_k * Xpad(+off)
// 8 warps (2M x 4N), warp tile 64x32, mma m16n8k16 bf16, K-chunk 64,
// 3-stage cp.async pipeline, ldmatrix fragments.
// mode 0: bf16 padded [p][co]; mode 1: bf16 unpadded [q][co].
// ---------------------------------------------------------------------------
#define KS      72                      // halves per smem row (64 + 8 pad)
#define STAGEH  (2 * 128 * KS)          // halves per stage (A tile + B tile)
#define OSTRIDE 132

__global__ void __launch_bounds__(256, 2)
conv_gemm_kernel(LevelParams l0, LevelParams l1, LevelParams l2, int mode)
{
    extern __shared__ __nv_bfloat16 dsm[];   // 3 stages of [A(128xKS) | B(128xKS)]

    const int x = blockIdx.x;
    const LevelParams L = (x >= l2.start) ? l2 : ((x >= l1.start) ? l1 : l0);

    const int idx  = x - L.start;
    const int tile = idx % L.tiles;
    const int rest = idx / L.tiles;
    const int cog  = rest % L.cgrp;
    const int n    = rest / L.cgrp;

    const int C = L.C, W = L.W, Wp = L.Wp, Np = L.Np;
    const int p0  = tile * 128;
    const int co0 = cog * 128;

    const int tid    = threadIdx.x;
    const int lane   = tid & 31;
    const int wid    = tid >> 5;
    const int warp_m = wid >> 2;        // 0..1
    const int warp_n = wid & 3;         // 0..3

    const __nv_bfloat16* Ximg = L.X + (size_t)n * Np * C;
    const __nv_bfloat16* wrep = L.Wr;
    const int NC = 9 * (C >> 6);        // K-chunks of 64 ci

    float acc[4][4][4];
#pragma unroll
    for (int mi = 0; mi < 4; mi++)
#pragma unroll
        for (int ni = 0; ni < 4; ni++)
#pragma unroll
            for (int r = 0; r < 4; r++) acc[mi][ni][r] = 0.f;

    const uint32_t smem0 = smem_u32(dsm);

    auto load_chunk = [&](int c, int buf) {
        const int k   = c % 9;
        const int cic = c / 9;
        const int off = (k / 3 - 1) * Wp + (k % 3 - 1);
        const __nv_bfloat16* Asrc = wrep + ((size_t)k * C + co0) * C + cic * 64;
        const __nv_bfloat16* Bsrc = Ximg + (long long)(p0 + off) * C + cic * 64;
        const uint32_t sAb = smem0 + buf * (STAGEH * 2);
        const uint32_t sBb = sAb + 128 * KS * 2;
#pragma unroll
        for (int i = 0; i < 4; i++) {
            int e = tid + i * 256, r = e >> 3, f = e & 7;
            cp_async16(sAb + (r * KS + f * 8) * 2, Asrc + (size_t)r * C + f * 8);
            cp_async16(sBb + (r * KS + f * 8) * 2, Bsrc + (long long)r * C + f * 8);
        }
        cp_commit();
    };

    // per-thread ldmatrix byte offsets (stage-relative)
    uint32_t aOff[4], bOff[2];
#pragma unroll
    for (int mi = 0; mi < 4; mi++) {
        int row = warp_m * 64 + mi * 16 + (lane & 15);
        aOff[mi] = (uint32_t)((row * KS + ((lane >> 4) << 3)) * 2);
    }
#pragma unroll
    for (int np = 0; np < 2; np++) {
        int px = warp_n * 32 + np * 16 + ((lane >> 4) << 3) + (lane & 7);
        bOff[np] = (uint32_t)((px * KS + (((lane >> 3) & 1) << 3)) * 2) + 128 * KS * 2;
    }

    load_chunk(0, 0);
    if (NC > 1) load_chunk(1, 1);

    int buf = 0;
    for (int c = 0; c < NC; c++) {
        if (c + 1 < NC)
            asm volatile("cp.async.wait_group 1;" ::: "memory");
        else
            asm volatile("cp.async.wait_group 0;" ::: "memory");
        __syncthreads();

        if (c + 2 < NC) {
            int nb = buf + 2; if (nb >= 3) nb -= 3;
            load_chunk(c + 2, nb);
        }

        const uint32_t sbase = smem0 + buf * (STAGEH * 2);
#pragma unroll
        for (int ks = 0; ks < 4; ks++) {
            const uint32_t ko = ks * 32;    // 16 halves
            uint32_t af[4][4], bf[2][4];
#pragma unroll
            for (int mi = 0; mi < 4; mi++)
                ldsm_x4(af[mi][0], af[mi][1], af[mi][2], af[mi][3],
                        sbase + aOff[mi] + ko);
#pragma unroll
            for (int np = 0; np < 2; np++)
                ldsm_x4(bf[np][0], bf[np][1], bf[np][2], bf[np][3],
                        sbase + bOff[np] + ko);
#pragma unroll
            for (int mi = 0; mi < 4; mi++)
#pragma unroll
                for (int ni = 0; ni < 4; ni++)
                    mma_bf16(acc[mi][ni][0], acc[mi][ni][1], acc[mi][ni][2], acc[mi][ni][3],
                             af[mi][0], af[mi][1], af[mi][2], af[mi][3],
                             bf[ni >> 1][(ni & 1) * 2], bf[ni >> 1][(ni & 1) * 2 + 1]);
        }
        buf++; if (buf == 3) buf = 0;
    }
    __syncthreads();

    // ---- epilogue: BN+ReLU, stage [px][co] fp32 tile in smem ----
    float* st = (float*)dsm;
    {
        const int g  = lane >> 2;
        const int q2 = (lane & 3) << 1;
#pragma unroll
        for (int mi = 0; mi < 4; mi++) {
            const int col0 = warp_m * 64 + mi * 16 + g;
            const float s0 = __ldg(L.scale + co0 + col0),     b0 = __ldg(L.bias + co0 + col0);
            const float s1 = __ldg(L.scale + co0 + col0 + 8), b1 = __ldg(L.bias + co0 + col0 + 8);
#pragma unroll
            for (int ni = 0; ni < 4; ni++) {
                const int pxl = warp_n * 32 + ni * 8 + q2;
                st[pxl * OSTRIDE + col0]           = fmaxf(fmaf(acc[mi][ni][0], s0, b0), 0.f);
                st[(pxl + 1) * OSTRIDE + col0]     = fmaxf(fmaf(acc[mi][ni][1], s0, b0), 0.f);
                st[pxl * OSTRIDE + col0 + 8]       = fmaxf(fmaf(acc[mi][ni][2], s1, b1), 0.f);
                st[(pxl + 1) * OSTRIDE + col0 + 8] = fmaxf(fmaf(acc[mi][ni][3], s1, b1), 0.f);
            }
        }
    }
    __syncthreads();

#pragma unroll 1
    for (int i = 0; i < 16; i++) {
        int idx2 = tid + i * 256;
        int r = idx2 >> 5, f = idx2 & 31;
        int p = p0 + r;
        if (p < Np) {
            int py = p / Wp, px = p - py * Wp;
            if (py >= 1 && py <= W && px >= 1 && px <= W) {
                float4 v = *(const float4*)&st[r * OSTRIDE + f * 4];
                __nv_bfloat162 h0 = __floats2bfloat162_rn(v.x, v.y);
                __nv_bfloat162 h1 = __floats2bfloat162_rn(v.z, v.w);
                uint2 pk;
                pk.x = *reinterpret_cast<uint32_t*>(&h0);
                pk.y = *reinterpret_cast<uint32_t*>(&h1);
                if (mode == 0) {
                    __nv_bfloat16* Yb = (__nv_bfloat16*)L.Y + (size_t)n * Np * C;
                    *(uint2*)&Yb[(size_t)p * C + co0 + f * 4] = pk;
                } else {
                    __nv_bfloat16* Yb = (__nv_bfloat16*)L.Y + (size_t)n * (size_t)(W * W) * C;
                    *(uint2*)&Yb[((size_t)(py - 1) * W + (px - 1)) * C + co0 + f * 4] = pk;
                }
            }
        }
    }
}

// ---------------------------------------------------------------------------
// 1x1 conv (C->5) + decode + sigmoid. warp-per-pixel, y2 bf16 [n][q][C].
// ---------------------------------------------------------------------------
__global__ void __launch_bounds__(256)
conv1x1_decode_kernel(const __nv_bfloat16* __restrict__ y2,
                      const float* __restrict__ wf,
                      const float* __restrict__ bf,
                      float* __restrict__ out,
                      int C, int W, int HW, int aoff, float stride)
{
    __shared__ float s_wf[5 * 512];
    for (int t = threadIdx.x; t < 5 * C; t += 256) s_wf[t] = wf[t];
    __syncthreads();

    const int wid  = threadIdx.x >> 5;
    const int lane = threadIdx.x & 31;
    const int q = blockIdx.x * 8 + wid;
    const int n = blockIdx.y;
    if (q >= HW) return;

    const __nv_bfloat16* yq = y2 + ((size_t)n * HW + q) * C;
    float a[5] = {0.f, 0.f, 0.f, 0.f, 0.f};
    const int iters = C >> 7;
    for (int it = 0; it < iters; it++) {
        int cb = it * 128 + lane * 4;
        uint2 vp = *(const uint2*)(yq + cb);
        __nv_bfloat162 h0 = *reinterpret_cast<__nv_bfloat162*>(&vp.x);
        __nv_bfloat162 h1 = *reinterpret_cast<__nv_bfloat162*>(&vp.y);
        float2 f0 = __bfloat1622float2(h0);
        float2 f1 = __bfloat1622float2(h1);
#pragma unroll
        for (int j = 0; j < 5; j++) {
            const float* wj = s_wf + j * C + cb;
            a[j] += f0.x * wj[0] + f0.y * wj[1] + f1.x * wj[2] + f1.y * wj[3];
        }
    }
#pragma unroll
    for (int j = 0; j < 5; j++)
#pragma unroll
        for (int o = 16; o; o >>= 1)
            a[j] += __shfl_xor_sync(0xffffffffu, a[j], o);

    if (lane == 0) {
        float a0 = a[0] + bf[0], a1 = a[1] + bf[1], a2 = a[2] + bf[2];
        float a3 = a[3] + bf[3], a4 = a[4] + bf[4];
        int py = q / W, px = q - py * W;
        float ax = px + 0.5f, ay = py + 0.5f;
        float cx = (ax + 0.5f * (a2 - a0)) * stride;
        float cy = (ay + 0.5f * (a3 - a1)) * stride;
        float bw = (a2 + a0) * stride;
        float bh = (a3 + a1) * stride;
        float cls = 1.f / (1.f + expf(-a4));
        size_t base = (size_t)n * 5 * ATOT + (size_t)aoff + q;
        out[base]                    = cx;
        out[base + (size_t)ATOT]     = cy;
        out[base + 2 * (size_t)ATOT] = bw;
        out[base + 3 * (size_t)ATOT] = bh;
        out[base + 4 * (size_t)ATOT] = cls;
    }
}

// ---------------------------------------------------------------------------
// Host
// ---------------------------------------------------------------------------
#define CONV_SMEM (3 * STAGEH * 2)   // 110,592 B

extern "C" void kernel_launch(void* const* d_in, const int* in_sizes, int n_in,
                              void* d_out, int out_size)
{
    // lazy one-time resource init (streams/events created on the correctness
    // run, before graph capture; reused as-is during capture)
    static cudaStream_t s1 = nullptr, s2 = nullptr;
    static cudaEvent_t evr = nullptr, ed1 = nullptr, ed2 = nullptr;
    if (!s1) {
        cudaStreamCreateWithFlags(&s1, cudaStreamNonBlocking);
        cudaStreamCreateWithFlags(&s2, cudaStreamNonBlocking);
        cudaEventCreateWithFlags(&evr, cudaEventDisableTiming);
        cudaEventCreateWithFlags(&ed1, cudaEventDisableTiming);
        cudaEventCreateWithFlags(&ed2, cudaEventDisableTiming);
        cudaFuncSetAttribute(conv_gemm_kernel,
                             cudaFuncAttributeMaxDynamicSharedMemorySize, CONV_SMEM);
    }

    __nv_bfloat16 *xpad, *ypad, *wr1, *wr2, *y2;
    cudaGetSymbolAddress((void**)&xpad, g_xpad);
    cudaGetSymbolAddress((void**)&ypad, g_ypad);
    cudaGetSymbolAddress((void**)&y2,   g_y2);
    cudaGetSymbolAddress((void**)&wr1,  g_wr1);
    cudaGetSymbolAddress((void**)&wr2,  g_wr2);

    const int B = in_sizes[0] / (128 * 160 * 160);
    float* out = (float*)d_out;

    // level tables, index: 0=p3, 1=p4, 2=p5
    const int   Cs[3]   = {128, 256, 512};
    const int   Ws[3]   = {160, 80, 40};
    const int   xin[3]  = {0, 1, 2};
    const int   widx[3] = {3, 11, 19};
    const int   xoff[3] = {OFF_P3, OFF_P4, OFF_P5};
    const int   y2off[3]= {Y2_P3, Y2_P4, Y2_P5};
    const int   wroff[3]= {WR_P3, WR_P4, WR_P5};
    const int   aoff[3] = {0, 25600, 32000};
    const float strd[3] = {8.f, 16.f, 32.f};

    // fork: all 3 level-chains start after the capture-origin point
    cudaEventRecord(evr, 0);
    cudaStreamWaitEvent(s1, evr, 0);
    cudaStreamWaitEvent(s2, evr, 0);

    const cudaStream_t lvlStream[3] = {(cudaStream_t)0, s1, s2};

    for (int i = 0; i < 3; i++) {
        const int C = Cs[i], W = Ws[i], Wp = W + 2, Np = Wp * Wp, HW = W * W;
        const int tiles = (Np + 127) / 128, cgrp = C / 128;
        cudaStream_t st = lvlStream[i];

        // wrepack (both convs)
        const int wtot = 9 * C * C;
        wrepack_kernel<<<(wtot + 255) / 256, 256, 0, st>>>(
            (const float*)d_in[widx[i] + 0], wr1 + wroff[i], C);
        wrepack_kernel<<<(wtot + 255) / 256, 256, 0, st>>>(
            (const float*)d_in[widx[i] + 3], wr2 + wroff[i], C);

        // pad+transpose input
        dim3 gp(HW / 32, C / 64, B);
        pad_transpose_kernel<<<gp, dim3(32, 8), 0, st>>>(
            (const float*)d_in[xin[i]], xpad + xoff[i], C, W, W, Wp, Np);

        // per-level conv1 -> conv2 on this stream
        LevelParams L1 = { xpad + xoff[i], wr1 + wroff[i],
            (const float*)d_in[widx[i] + 1], (const float*)d_in[widx[i] + 2],
            (void*)(ypad + xoff[i]), C, W, Wp, Np, 0, tiles, cgrp };
        LevelParams L2 = { ypad + xoff[i], wr2 + wroff[i],
            (const float*)d_in[widx[i] + 4], (const float*)d_in[widx[i] + 5],
            (void*)(y2 + y2off[i]), C, W, Wp, Np, 0, tiles, cgrp };
        LevelParams Ldummy = L1;
        Ldummy.start = INT_MAX;

        const int grid = tiles * cgrp * B;
        conv_gemm_kernel<<<grid, 256, CONV_SMEM, st>>>(L1, Ldummy, Ldummy, 0);
        conv_gemm_kernel<<<grid, 256, CONV_SMEM, st>>>(L2, Ldummy, Ldummy, 1);

        // decode
        dim3 gd((HW + 7) / 8, B);
        conv1x1_decode_kernel<<<gd, 256, 0, st>>>(
            y2 + y2off[i], (const float*)d_in[widx[i] + 6],
            (const float*)d_in[widx[i] + 7], out, C, W, HW, aoff[i], strd[i]);
    }

    // join back to the captured origin stream
    cudaEventRecord(ed1, s1);
    cudaEventRecord(ed2, s2);
    cudaStreamWaitEvent(0, ed1, 0);
    cudaStreamWaitEvent(0, ed2, 0);
}

// round 17
// speedup vs baseline: 1.1093x; 1.0185x over previous
#include <cuda_runtime.h>
#include <cuda_bf16.h>
#include <math.h>
#include <stdint.h>
#include <limits.h>

// ===========================================================================
// YOLOv8 head via bf16 mma.sync implicit GEMM (shifted-GEMM conv).
//   conv3x3(pad1) == sum over 9 kernel offsets k of GEMM:
//      D[co, q] += W_k[co, ci] * Xpad[p(q) + off_k, ci]
// R17: R16 (q-indexed interior-only GEMM output, -4.3% conv CTAs) with the
//      B-tile cp.async loop fixed to 4 iterations (1024 float4 = 128 rows;
//      R16's 8-iter loop overran smem -> IMA). R15 stream chains kept.
// ===========================================================================

#define ATOT 33600

// per-level xpad/ypad region offsets (halves)
#define OFF_P3 262144
#define OFF_P4 27398144
#define OFF_P5 41431040
#define XPAD_TOTAL 48918528

// per-level y2 offsets (bf16 elements)
#define Y2_P3 0
#define Y2_P4 26214400
#define Y2_P5 39321600
#define Y2_TOTAL 45875200

// per-level wrep offsets (halves)
#define WR_P5 0
#define WR_P4 2359296
#define WR_P3 2949120
#define WR_TOTAL 3096576

__device__ __align__(256) __nv_bfloat16 g_xpad[XPAD_TOTAL];
__device__ __align__(256) __nv_bfloat16 g_ypad[XPAD_TOTAL];
__device__ __align__(256) __nv_bfloat16 g_y2  [Y2_TOTAL];
__device__ __align__(256) __nv_bfloat16 g_wr1 [WR_TOTAL];
__device__ __align__(256) __nv_bfloat16 g_wr2 [WR_TOTAL];

struct LevelParams {
    const __nv_bfloat16* X;
    const __nv_bfloat16* Wr;
    const float* scale;
    const float* bias;
    void* Y;
    int C, W, Wp, Np, HW;
    int start;      // first flat CTA index of this level
    int tiles;      // pixel tiles = ceil(HW/128)
    int cgrp;       // C / 128
    int wshift;     // W = 5 << wshift
};

__device__ __forceinline__ uint32_t smem_u32(const void* p) {
    return (uint32_t)__cvta_generic_to_shared(p);
}
__device__ __forceinline__ void cp_async16(uint32_t dst, const void* src) {
    asm volatile("cp.async.cg.shared.global [%0], [%1], 16;"
                 :: "r"(dst), "l"(__cvta_generic_to_global(src)) : "memory");
}
__device__ __forceinline__ void cp_commit() {
    asm volatile("cp.async.commit_group;" ::: "memory");
}
__device__ __forceinline__ void ldsm_x4(uint32_t& r0, uint32_t& r1,
                                        uint32_t& r2, uint32_t& r3, uint32_t a) {
    asm volatile("ldmatrix.sync.aligned.m8n8.x4.shared.b16 {%0,%1,%2,%3}, [%4];"
                 : "=r"(r0), "=r"(r1), "=r"(r2), "=r"(r3) : "r"(a));
}
__device__ __forceinline__ void mma_bf16(float& d0, float& d1, float& d2, float& d3,
                                         uint32_t a0, uint32_t a1, uint32_t a2, uint32_t a3,
                                         uint32_t b0, uint32_t b1) {
    asm volatile(
        "mma.sync.aligned.m16n8k16.row.col.f32.bf16.bf16.f32 "
        "{%0,%1,%2,%3}, {%4,%5,%6,%7}, {%8,%9}, {%0,%1,%2,%3};"
        : "+f"(d0), "+f"(d1), "+f"(d2), "+f"(d3)
        : "r"(a0), "r"(a1), "r"(a2), "r"(a3), "r"(b0), "r"(b1));
}
// unsigned q/5 via magic multiply
__device__ __forceinline__ int div5u(int q) {
    return (int)(__umulhi((unsigned)q, 0xCCCCCCCDu) >> 2);
}

// ---------------------------------------------------------------------------
// weight repack: W(co,ci,3,3) fp32 -> Wrep[k][co][ci] bf16 (thread-per-output)
// ---------------------------------------------------------------------------
__global__ void wrepack_kernel(const float* __restrict__ w,
                               __nv_bfloat16* __restrict__ wr, int C)
{
    int o = blockIdx.x * blockDim.x + threadIdx.x;   // k*C*C + e
    const int plane = C * C;
    if (o >= 9 * plane) return;
    int k = o / plane;
    int e = o - k * plane;
    wr[o] = __float2bfloat16_rn(w[(size_t)e * 9 + k]);
}

// ---------------------------------------------------------------------------
// pad+transpose: NCHW fp32 -> Xpad[n][p][ci] bf16 (interior pixels only).
// ---------------------------------------------------------------------------
__global__ void pad_transpose_kernel(const float* __restrict__ in,
                                     __nv_bfloat16* __restrict__ Xp,
                                     int C, int H, int W, int Wp, int Np)
{
    __shared__ float t[64][33];
    const int HW = H * W;
    const int q0 = blockIdx.x * 32;
    const int c0 = blockIdx.y * 64;
    const int n  = blockIdx.z;
    const int tx = threadIdx.x, ty = threadIdx.y;

    const float* inN = in + (size_t)n * C * HW;
#pragma unroll
    for (int j = 0; j < 8; j++) {
        int cc = ty + j * 8;
        t[cc][tx] = inN[(size_t)(c0 + cc) * HW + q0 + tx];
    }
    __syncthreads();

    __nv_bfloat16* XpN = Xp + (size_t)n * Np * C;
#pragma unroll
    for (int j = 0; j < 4; j++) {
        int qq = ty + j * 8;
        int q  = q0 + qq;
        int py = q / W, px = q - py * W;
        int p  = (py + 1) * Wp + px + 1;
        __nv_bfloat162 h = __floats2bfloat162_rn(t[2 * tx][qq], t[2 * tx + 1][qq]);
        *(uint32_t*)&XpN[(size_t)p * C + c0 + 2 * tx] = *reinterpret_cast<uint32_t*>(&h);
    }
}

// ---------------------------------------------------------------------------
// conv GEMM, q-indexed interior output: D[128 co x 128 q] accumulated over
// 9 offsets x ci-chunks. 8 warps (2Mx4N), warp tile 64x32, m16n8k16 bf16,
// K-chunk 64, 3-stage cp.async, ldmatrix fragments.
// mode 0: bf16 padded [p(q)][co]; mode 1: bf16 unpadded [q][co].
// ---------------------------------------------------------------------------
#define KS      72
#define STAGEH  (2 * 128 * KS)
#define OSTRIDE 132

__global__ void __launch_bounds__(256, 2)
conv_gemm_kernel(LevelParams l0, LevelParams l1, LevelParams l2, int mode)
{
    extern __shared__ __nv_bfloat16 dsm[];

    const int x = blockIdx.x;
    const LevelParams L = (x >= l2.start) ? l2 : ((x >= l1.start) ? l1 : l0);

    const int idx  = x - L.start;
    const int tile = idx % L.tiles;
    const int rest = idx / L.tiles;
    const int cog  = rest % L.cgrp;
    const int n    = rest / L.cgrp;

    const int C = L.C, W = L.W, Wp = L.Wp, Np = L.Np, HW = L.HW;
    const int wsh = L.wshift;
    const int q0  = tile * 128;
    const int co0 = cog * 128;

    const int tid    = threadIdx.x;
    const int lane   = tid & 31;
    const int wid    = tid >> 5;
    const int warp_m = wid >> 2;
    const int warp_n = wid & 3;

    const __nv_bfloat16* Ximg = L.X + (size_t)n * Np * C;
    const __nv_bfloat16* wrep = L.Wr;
    const int NC = 9 * (C >> 6);

    float acc[4][4][4];
#pragma unroll
    for (int mi = 0; mi < 4; mi++)
#pragma unroll
        for (int ni = 0; ni < 4; ni++)
#pragma unroll
            for (int r = 0; r < 4; r++) acc[mi][ni][r] = 0.f;

    const uint32_t smem0 = smem_u32(dsm);

    // per-thread B row (fixed across chunks): each of 4 iterations covers
    // 256 float4 = 32 rows; this thread touches rows r_i = (tid>>3) + i*32.
    auto load_chunk = [&](int c, int buf) {
        const int k   = c % 9;
        const int cic = c / 9;
        const int off = (k / 3 - 1) * Wp + (k % 3 - 1);
        const __nv_bfloat16* Asrc = wrep + ((size_t)k * C + co0) * C + cic * 64;
        const __nv_bfloat16* Bbase = Ximg + cic * 64;
        const uint32_t sAb = smem0 + buf * (STAGEH * 2);
        const uint32_t sBb = sAb + 128 * KS * 2;
#pragma unroll
        for (int i = 0; i < 4; i++) {
            int e = tid + i * 256, r = e >> 3, f = e & 7;   // r in [0,128)
            cp_async16(sAb + (r * KS + f * 8) * 2, Asrc + (size_t)r * C + f * 8);
            int q = q0 + r; if (q >= HW) q = HW - 1;        // p5 overhang clamp
            int py = div5u(q) >> wsh;                        // q / W
            int p  = (py + 1) * Wp + (q - py * W) + 1;       // padded pixel
            cp_async16(sBb + (r * KS + f * 8) * 2,
                       Bbase + (long long)(p + off) * C + f * 8);
        }
        cp_commit();
    };

    // per-thread ldmatrix byte offsets (stage-relative)
    uint32_t aOff[4], bOff[2];
#pragma unroll
    for (int mi = 0; mi < 4; mi++) {
        int row = warp_m * 64 + mi * 16 + (lane & 15);
        aOff[mi] = (uint32_t)((row * KS + ((lane >> 4) << 3)) * 2);
    }
#pragma unroll
    for (int np = 0; np < 2; np++) {
        int px = warp_n * 32 + np * 16 + ((lane >> 4) << 3) + (lane & 7);
        bOff[np] = (uint32_t)((px * KS + (((lane >> 3) & 1) << 3)) * 2) + 128 * KS * 2;
    }

    load_chunk(0, 0);
    if (NC > 1) load_chunk(1, 1);

    int buf = 0;
    for (int c = 0; c < NC; c++) {
        if (c + 1 < NC)
            asm volatile("cp.async.wait_group 1;" ::: "memory");
        else
            asm volatile("cp.async.wait_group 0;" ::: "memory");
        __syncthreads();

        if (c + 2 < NC) {
            int nb = buf + 2; if (nb >= 3) nb -= 3;
            load_chunk(c + 2, nb);
        }

        const uint32_t sbase = smem0 + buf * (STAGEH * 2);
#pragma unroll
        for (int ks = 0; ks < 4; ks++) {
            const uint32_t ko = ks * 32;
            uint32_t af[4][4], bf[2][4];
#pragma unroll
            for (int mi = 0; mi < 4; mi++)
                ldsm_x4(af[mi][0], af[mi][1], af[mi][2], af[mi][3],
                        sbase + aOff[mi] + ko);
#pragma unroll
            for (int np = 0; np < 2; np++)
                ldsm_x4(bf[np][0], bf[np][1], bf[np][2], bf[np][3],
                        sbase + bOff[np] + ko);
#pragma unroll
            for (int mi = 0; mi < 4; mi++)
#pragma unroll
                for (int ni = 0; ni < 4; ni++)
                    mma_bf16(acc[mi][ni][0], acc[mi][ni][1], acc[mi][ni][2], acc[mi][ni][3],
                             af[mi][0], af[mi][1], af[mi][2], af[mi][3],
                             bf[ni >> 1][(ni & 1) * 2], bf[ni >> 1][(ni & 1) * 2 + 1]);
        }
        buf++; if (buf == 3) buf = 0;
    }
    __syncthreads();

    // ---- epilogue: BN+ReLU, stage [q][co] fp32 tile in smem ----
    float* st = (float*)dsm;
    {
        const int g  = lane >> 2;
        const int q2 = (lane & 3) << 1;
#pragma unroll
        for (int mi = 0; mi < 4; mi++) {
            const int col0 = warp_m * 64 + mi * 16 + g;
            const float s0 = __ldg(L.scale + co0 + col0),     b0 = __ldg(L.bias + co0 + col0);
            const float s1 = __ldg(L.scale + co0 + col0 + 8), b1 = __ldg(L.bias + co0 + col0 + 8);
#pragma unroll
            for (int ni = 0; ni < 4; ni++) {
                const int pxl = warp_n * 32 + ni * 8 + q2;
                st[pxl * OSTRIDE + col0]           = fmaxf(fmaf(acc[mi][ni][0], s0, b0), 0.f);
                st[(pxl + 1) * OSTRIDE + col0]     = fmaxf(fmaf(acc[mi][ni][1], s0, b0), 0.f);
                st[pxl * OSTRIDE + col0 + 8]       = fmaxf(fmaf(acc[mi][ni][2], s1, b1), 0.f);
                st[(pxl + 1) * OSTRIDE + col0 + 8] = fmaxf(fmaf(acc[mi][ni][3], s1, b1), 0.f);
            }
        }
    }
    __syncthreads();

#pragma unroll 1
    for (int i = 0; i < 16; i++) {
        int idx2 = tid + i * 256;
        int r = idx2 >> 5, f = idx2 & 31;
        int q = q0 + r;
        if (q < HW) {
            float4 v = *(const float4*)&st[r * OSTRIDE + f * 4];
            __nv_bfloat162 h0 = __floats2bfloat162_rn(v.x, v.y);
            __nv_bfloat162 h1 = __floats2bfloat162_rn(v.z, v.w);
            uint2 pk;
            pk.x = *reinterpret_cast<uint32_t*>(&h0);
            pk.y = *reinterpret_cast<uint32_t*>(&h1);
            if (mode == 0) {
                int py = div5u(q) >> wsh;
                int p  = (py + 1) * Wp + (q - py * W) + 1;
                __nv_bfloat16* Yb = (__nv_bfloat16*)L.Y + (size_t)n * Np * C;
                *(uint2*)&Yb[(size_t)p * C + co0 + f * 4] = pk;
            } else {
                __nv_bfloat16* Yb = (__nv_bfloat16*)L.Y + (size_t)n * HW * C;
                *(uint2*)&Yb[(size_t)q * C + co0 + f * 4] = pk;
            }
        }
    }
}

// ---------------------------------------------------------------------------
// 1x1 conv (C->5) + decode + sigmoid. warp-per-pixel, y2 bf16 [n][q][C].
// ---------------------------------------------------------------------------
__global__ void __launch_bounds__(256)
conv1x1_decode_kernel(const __nv_bfloat16* __restrict__ y2,
                      const float* __restrict__ wf,
                      const float* __restrict__ bf,
                      float* __restrict__ out,
                      int C, int W, int HW, int aoff, float stride)
{
    __shared__ float s_wf[5 * 512];
    for (int t = threadIdx.x; t < 5 * C; t += 256) s_wf[t] = wf[t];
    __syncthreads();

    const int wid  = threadIdx.x >> 5;
    const int lane = threadIdx.x & 31;
    const int q = blockIdx.x * 8 + wid;
    const int n = blockIdx.y;
    if (q >= HW) return;

    const __nv_bfloat16* yq = y2 + ((size_t)n * HW + q) * C;
    float a[5] = {0.f, 0.f, 0.f, 0.f, 0.f};
    const int iters = C >> 7;
    for (int it = 0; it < iters; it++) {
        int cb = it * 128 + lane * 4;
        uint2 vp = *(const uint2*)(yq + cb);
        __nv_bfloat162 h0 = *reinterpret_cast<__nv_bfloat162*>(&vp.x);
        __nv_bfloat162 h1 = *reinterpret_cast<__nv_bfloat162*>(&vp.y);
        float2 f0 = __bfloat1622float2(h0);
        float2 f1 = __bfloat1622float2(h1);
#pragma unroll
        for (int j = 0; j < 5; j++) {
            const float* wj = s_wf + j * C + cb;
            a[j] += f0.x * wj[0] + f0.y * wj[1] + f1.x * wj[2] + f1.y * wj[3];
        }
    }
#pragma unroll
    for (int j = 0; j < 5; j++)
#pragma unroll
        for (int o = 16; o; o >>= 1)
            a[j] += __shfl_xor_sync(0xffffffffu, a[j], o);

    if (lane == 0) {
        float a0 = a[0] + bf[0], a1 = a[1] + bf[1], a2 = a[2] + bf[2];
        float a3 = a[3] + bf[3], a4 = a[4] + bf[4];
        int py = q / W, px = q - py * W;
        float ax = px + 0.5f, ay = py + 0.5f;
        float cx = (ax + 0.5f * (a2 - a0)) * stride;
        float cy = (ay + 0.5f * (a3 - a1)) * stride;
        float bw = (a2 + a0) * stride;
        float bh = (a3 + a1) * stride;
        float cls = 1.f / (1.f + expf(-a4));
        size_t base = (size_t)n * 5 * ATOT + (size_t)aoff + q;
        out[base]                    = cx;
        out[base + (size_t)ATOT]     = cy;
        out[base + 2 * (size_t)ATOT] = bw;
        out[base + 3 * (size_t)ATOT] = bh;
        out[base + 4 * (size_t)ATOT] = cls;
    }
}

// ---------------------------------------------------------------------------
// Host
// ---------------------------------------------------------------------------
#define CONV_SMEM (3 * STAGEH * 2)   // 110,592 B

extern "C" void kernel_launch(void* const* d_in, const int* in_sizes, int n_in,
                              void* d_out, int out_size)
{
    static cudaStream_t s1 = nullptr, s2 = nullptr;
    static cudaEvent_t evr = nullptr, ed1 = nullptr, ed2 = nullptr;
    if (!s1) {
        cudaStreamCreateWithFlags(&s1, cudaStreamNonBlocking);
        cudaStreamCreateWithFlags(&s2, cudaStreamNonBlocking);
        cudaEventCreateWithFlags(&evr, cudaEventDisableTiming);
        cudaEventCreateWithFlags(&ed1, cudaEventDisableTiming);
        cudaEventCreateWithFlags(&ed2, cudaEventDisableTiming);
        cudaFuncSetAttribute(conv_gemm_kernel,
                             cudaFuncAttributeMaxDynamicSharedMemorySize, CONV_SMEM);
    }

    __nv_bfloat16 *xpad, *ypad, *wr1, *wr2, *y2;
    cudaGetSymbolAddress((void**)&xpad, g_xpad);
    cudaGetSymbolAddress((void**)&ypad, g_ypad);
    cudaGetSymbolAddress((void**)&y2,   g_y2);
    cudaGetSymbolAddress((void**)&wr1,  g_wr1);
    cudaGetSymbolAddress((void**)&wr2,  g_wr2);

    const int B = in_sizes[0] / (128 * 160 * 160);
    float* out = (float*)d_out;

    // level tables, index: 0=p3, 1=p4, 2=p5
    const int   Cs[3]   = {128, 256, 512};
    const int   Ws[3]   = {160, 80, 40};
    const int   wsh[3]  = {5, 4, 3};            // W = 5 << wsh
    const int   xin[3]  = {0, 1, 2};
    const int   widx[3] = {3, 11, 19};
    const int   xoff[3] = {OFF_P3, OFF_P4, OFF_P5};
    const int   y2off[3]= {Y2_P3, Y2_P4, Y2_P5};
    const int   wroff[3]= {WR_P3, WR_P4, WR_P5};
    const int   aoff[3] = {0, 25600, 32000};
    const float strd[3] = {8.f, 16.f, 32.f};

    cudaEventRecord(evr, 0);
    cudaStreamWaitEvent(s1, evr, 0);
    cudaStreamWaitEvent(s2, evr, 0);

    const cudaStream_t lvlStream[3] = {(cudaStream_t)0, s1, s2};

    for (int i = 0; i < 3; i++) {
        const int C = Cs[i], W = Ws[i], Wp = W + 2, Np = Wp * Wp, HW = W * W;
        const int tiles = (HW + 127) / 128, cgrp = C / 128;
        cudaStream_t st = lvlStream[i];

        const int wtot = 9 * C * C;
        wrepack_kernel<<<(wtot + 255) / 256, 256, 0, st>>>(
            (const float*)d_in[widx[i] + 0], wr1 + wroff[i], C);
        wrepack_kernel<<<(wtot + 255) / 256, 256, 0, st>>>(
            (const float*)d_in[widx[i] + 3], wr2 + wroff[i], C);

        dim3 gp(HW / 32, C / 64, B);
        pad_transpose_kernel<<<gp, dim3(32, 8), 0, st>>>(
            (const float*)d_in[xin[i]], xpad + xoff[i], C, W, W, Wp, Np);

        LevelParams L1 = { xpad + xoff[i], wr1 + wroff[i],
            (const float*)d_in[widx[i] + 1], (const float*)d_in[widx[i] + 2],
            (void*)(ypad + xoff[i]), C, W, Wp, Np, HW, 0, tiles, cgrp, wsh[i] };
        LevelParams L2 = { ypad + xoff[i], wr2 + wroff[i],
            (const float*)d_in[widx[i] + 4], (const float*)d_in[widx[i] + 5],
            (void*)(y2 + y2off[i]), C, W, Wp, Np, HW, 0, tiles, cgrp, wsh[i] };
        LevelParams Ldummy = L1;
        Ldummy.start = INT_MAX;

        const int grid = tiles * cgrp * B;
        conv_gemm_kernel<<<grid, 256, CONV_SMEM, st>>>(L1, Ldummy, Ldummy, 0);
        conv_gemm_kernel<<<grid, 256, CONV_SMEM, st>>>(L2, Ldummy, Ldummy, 1);

        dim3 gd((HW + 7) / 8, B);
        conv1x1_decode_kernel<<<gd, 256, 0, st>>>(
            y2 + y2off[i], (const float*)d_in[widx[i] + 6],
            (const float*)d_in[widx[i] + 7], out, C, W, HW, aoff[i], strd[i]);
    }

    cudaEventRecord(ed1, s1);
    cudaEventRecord(ed2, s2);
    cudaStreamWaitEvent(0, ed1, 0);
    cudaStreamWaitEvent(0, ed2, 0);
}